// round 1
// baseline (speedup 1.0000x reference)
#include <cuda_runtime.h>
#include <math.h>
#include <stdint.h>

// ---------------- problem constants ----------------
#define NPAIRS_MAX 200000
#define MAX_NB 6
#define NWARPS 8          // warps per block in the MLP kernel
#define MLP_BLOCKS 148
#define PI_F 3.14159265358979323846f

// feature layout: [0,200) atom ACSF (k*10+t), [200,300) pair APSF (k*10+t),
// [300] Zj, [301,311) onehot j, [311] Zk, [312,322) onehot k
#define FEAT 322
#define XPAD 328

// shared offsets (floats)
#define OFF_W1   0
#define OFF_W2   20608
#define OFF_W3   24704
#define OFF_WO   28800
#define OFF_B1   28864
#define OFF_G1   28928
#define OFF_BE1  28992
#define OFF_B2   29056
#define OFF_G2   29120
#define OFF_BE2  29184
#define OFF_B3   29248
#define OFF_G3   29312
#define OFF_BE3  29376
#define OFF_BO   29440
#define OFF_X    29441
#define SMEM_FLOATS (OFF_X + NWARPS * XPAD)   // 32065
#define SMEM_BYTES  (SMEM_FLOATS * 4)         // 128260

// ---------------- device globals (no cudaMalloc allowed) ----------------
__device__ float  g_box[9];
__device__ float  g_binv[9];
__device__ int    g_count;
__device__ double g_sum;
__device__ int    g_p0[NPAIRS_MAX];
__device__ int    g_p1[NPAIRS_MAX];
__device__ float4 g_rec[NPAIRS_MAX];   // rij.x, rij.y, rij.z, w
__device__ float  g_dn[NPAIRS_MAX];

__constant__ float c_zidx[10] = {1.f, 3.f, 5.f, 6.f, 7.f, 8.f, 9.f, 11.f, 15.f, 16.f};

// ---------------- helpers ----------------
__device__ __forceinline__ float3 pbc3(float dx, float dy, float dz,
                                       const float* B, const float* Bi) {
    // ds = dr @ Binv (row vector), wrap, dr' = ds @ B
    float s0 = dx * Bi[0] + dy * Bi[3] + dz * Bi[6];
    float s1 = dx * Bi[1] + dy * Bi[4] + dz * Bi[7];
    float s2 = dx * Bi[2] + dy * Bi[5] + dz * Bi[8];
    s0 -= floorf(s0 + 0.5f);
    s1 -= floorf(s1 + 0.5f);
    s2 -= floorf(s2 + 0.5f);
    float3 r;
    r.x = s0 * B[0] + s1 * B[3] + s2 * B[6];
    r.y = s0 * B[1] + s1 * B[4] + s2 * B[7];
    r.z = s0 * B[2] + s1 * B[5] + s2 * B[8];
    return r;
}

__device__ __forceinline__ float warp_allreduce(float v) {
    v += __shfl_xor_sync(0xffffffffu, v, 16);
    v += __shfl_xor_sync(0xffffffffu, v, 8);
    v += __shfl_xor_sync(0xffffffffu, v, 4);
    v += __shfl_xor_sync(0xffffffffu, v, 2);
    v += __shfl_xor_sync(0xffffffffu, v, 1);
    return v;
}

// one warp: h = x@W + b ; layernorm ; relu ; write result to x[0..63]
__device__ __forceinline__ void dense_ln_relu_warp(
    const float* __restrict__ Ws, const float* __restrict__ b,
    const float* __restrict__ g, const float* __restrict__ be,
    float* x, int inDim, int lane)
{
    float a0 = b[lane];
    float a1 = b[lane + 32];
    const float* w0 = Ws + lane;
    const float* w1 = Ws + lane + 32;
#pragma unroll 4
    for (int i = 0; i < inDim; i++) {
        float xv = x[i];
        a0 = fmaf(xv, w0[i * 64], a0);
        a1 = fmaf(xv, w1[i * 64], a1);
    }
    float mu = warp_allreduce(a0 + a1) * (1.f / 64.f);
    float d0 = a0 - mu, d1 = a1 - mu;
    float var = warp_allreduce(d0 * d0 + d1 * d1) * (1.f / 64.f);
    float r = rsqrtf(var + 1e-6f);
    float y0 = fmaxf(d0 * r * g[lane] + be[lane], 0.f);
    float y1 = fmaxf(d1 * r * g[lane + 32] + be[lane + 32], 0.f);
    __syncwarp();
    x[lane] = y0;
    x[lane + 32] = y1;
    __syncwarp();
}

// ---------------- kernel 1: box inverse + reset ----------------
__global__ void k_setup(const float* __restrict__ box) {
    if (threadIdx.x == 0) {
        float b[9];
#pragma unroll
        for (int i = 0; i < 9; i++) { b[i] = box[i]; g_box[i] = b[i]; }
        float det = b[0] * (b[4] * b[8] - b[5] * b[7])
                  - b[1] * (b[3] * b[8] - b[5] * b[6])
                  + b[2] * (b[3] * b[7] - b[4] * b[6]);
        float id = 1.f / det;
        g_binv[0] = (b[4] * b[8] - b[5] * b[7]) * id;
        g_binv[1] = (b[2] * b[7] - b[1] * b[8]) * id;
        g_binv[2] = (b[1] * b[5] - b[2] * b[4]) * id;
        g_binv[3] = (b[5] * b[6] - b[3] * b[8]) * id;
        g_binv[4] = (b[0] * b[8] - b[2] * b[6]) * id;
        g_binv[5] = (b[2] * b[3] - b[0] * b[5]) * id;
        g_binv[6] = (b[3] * b[7] - b[4] * b[6]) * id;
        g_binv[7] = (b[1] * b[6] - b[0] * b[7]) * id;
        g_binv[8] = (b[0] * b[4] - b[1] * b[3]) * id;
        g_count = 0;
        g_sum = 0.0;
    }
}

// ---------------- kernel 2: filter + compact active pairs ----------------
__global__ void k_filter(const float* __restrict__ pos,
                         const float* __restrict__ valid,
                         const int* __restrict__ pairs,
                         const int* __restrict__ molid,
                         int npairs)
{
    int i = blockIdx.x * blockDim.x + threadIdx.x;
    if (i >= npairs) return;
    int p0 = pairs[3 * i];
    int p1 = pairs[3 * i + 1];
    if (p1 - p0 <= 0) { p0 -= 1; p1 -= 2; }
    if (p0 >= p1) return;                       // buffer_scales = 0
    float bs = valid[i];
    if (bs == 0.f) return;
    if (molid[p0] == molid[p1]) return;         // buffer_inter = 0

    float ax = pos[3 * p0], ay = pos[3 * p0 + 1], az = pos[3 * p0 + 2];
    float bx = pos[3 * p1], by = pos[3 * p1 + 1], bz = pos[3 * p1 + 2];
    float3 r = pbc3(bx - ax, by - ay, bz - az, g_box, g_binv);
    float cx = r.x + 1e-10f, cy = r.y + 1e-10f, cz = r.z + 1e-10f;
    float dn = sqrtf(cx * cx + cy * cy + cz * cz);
    if (dn > 5.0f) return;                      // cutoff = 0
    float cut = 0.5f * (1.f + cosf(PI_F * dn * (1.f / 5.f)));
    float w = bs * cut;
    if (w <= 0.f) return;

    int slot = atomicAdd(&g_count, 1);
    g_p0[slot] = p0;
    g_p1[slot] = p1;
    g_rec[slot] = make_float4(r.x, r.y, r.z, w);
    g_dn[slot] = dn;
}

// ---------------- kernel 3: features + MLP per active pair ----------------
__global__ __launch_bounds__(NWARPS * 32, 1)
void k_mlp(const float* __restrict__ pos,
           const int* __restrict__ topo,
           const int* __restrict__ atype,
           const float* __restrict__ W1, const float* __restrict__ b1,
           const float* __restrict__ g1, const float* __restrict__ be1,
           const float* __restrict__ W2, const float* __restrict__ b2,
           const float* __restrict__ g2, const float* __restrict__ be2,
           const float* __restrict__ W3, const float* __restrict__ b3,
           const float* __restrict__ g3, const float* __restrict__ be3,
           const float* __restrict__ Wo, const float* __restrict__ bo)
{
    extern __shared__ float sm[];
    int tid = threadIdx.x;

    // stage weights in shared (once per block)
    for (int i = tid; i < 20608; i += NWARPS * 32) sm[OFF_W1 + i] = W1[i];
    for (int i = tid; i < 4096; i += NWARPS * 32) {
        sm[OFF_W2 + i] = W2[i];
        sm[OFF_W3 + i] = W3[i];
    }
    if (tid < 64) {
        sm[OFF_WO + tid] = Wo[tid];
        sm[OFF_B1 + tid] = b1[tid]; sm[OFF_G1 + tid] = g1[tid]; sm[OFF_BE1 + tid] = be1[tid];
        sm[OFF_B2 + tid] = b2[tid]; sm[OFF_G2 + tid] = g2[tid]; sm[OFF_BE2 + tid] = be2[tid];
        sm[OFF_B3 + tid] = b3[tid]; sm[OFF_G3 + tid] = g3[tid]; sm[OFF_BE3 + tid] = be3[tid];
    }
    if (tid == 0) sm[OFF_BO] = bo[0];
    __syncthreads();

    float B[9], Bi[9];
#pragma unroll
    for (int i = 0; i < 9; i++) { B[i] = g_box[i]; Bi[i] = g_binv[i]; }

    int lane = tid & 31;
    int wid = tid >> 5;
    float* x = sm + OFF_X + wid * XPAD;
    int n = g_count;

    for (int pi = blockIdx.x * NWARPS + wid; pi < n; pi += gridDim.x * NWARPS) {
        int p0 = g_p0[pi];
        int p1 = g_p1[pi];
        float4 rec = g_rec[pi];
        float dn = g_dn[pi];
        float w = rec.w;
        float uinv = 1.f / (dn + 1e-10f);
        float ux = rec.x * uinv, uy = rec.y * uinv, uz = rec.z * uinv;

        for (int i = lane; i < FEAT; i += 32) x[i] = 0.f;
        __syncwarp();

        float p0x = pos[3 * p0], p0y = pos[3 * p0 + 1], p0z = pos[3 * p0 + 2];
        float p1x = pos[3 * p1], p1y = pos[3 * p1 + 1], p1z = pos[3 * p1 + 2];
        int t0 = atype[p0], t1 = atype[p1];

        // lanes 0..11 gather one neighbor each (2 atoms x 6 slots), in parallel
        int nbL = -1, ttL = 0;
        float nxL = 0.f, nyL = 0.f, nzL = 0.f;
        if (lane < 12) {
            int s = (lane >= 6) ? 1 : 0;
            int m = lane - 6 * s;
            int a = s ? p1 : p0;
            nbL = topo[a * MAX_NB + m];
            if (nbL >= 0) {
                nxL = pos[3 * nbL]; nyL = pos[3 * nbL + 1]; nzL = pos[3 * nbL + 2];
                ttL = atype[nbL];
            }
        }

#pragma unroll
        for (int e = 0; e < 12; e++) {
            int nbe = __shfl_sync(0xffffffffu, nbL, e);
            float ex = __shfl_sync(0xffffffffu, nxL, e);
            float ey = __shfl_sync(0xffffffffu, nyL, e);
            float ez = __shfl_sync(0xffffffffu, nzL, e);
            int te = __shfl_sync(0xffffffffu, ttL, e);
            if (nbe < 0) continue;
            int s = (e >= 6) ? 1 : 0;
            float cx = s ? p1x : p0x;
            float cy = s ? p1y : p0y;
            float cz = s ? p1z : p0z;
            float3 d = pbc3(ex - cx, ey - cy, ez - cz, B, Bi);
            float ddx = d.x + 1e-10f, ddy = d.y + 1e-10f, ddz = d.z + 1e-10f;
            float edn = sqrtf(ddx * ddx + ddy * ddy + ddz * ddz);

            // ACSF (atom env): f_cut gate (fx < 1), lanes 0..19 over mus
            float fx = edn * 0.2f;
            if (fx < 1.f) {
                float fc = 0.5f * (cosf(PI_F * fx) + 1.f);
                if (lane < 20) {
                    float dm = edn - (float)lane * (5.f / 19.f);
                    x[lane * 10 + te] += 0.5f * fc * expf(-100.f * dm * dm);
                }
            }
            // APSF (angular): exclude the pair atoms themselves, lanes 0..9 over mus
            if (nbe != p0 && nbe != p1) {
                float idn = 1.f / edn;
                float sgn = s ? -1.f : 1.f;
                float cg = (d.x * ux + d.y * uy + d.z * uz) * idn * sgn;
                if (lane < 10) {
                    float dm = cg - (-1.f + (float)lane * (2.f / 9.f));
                    x[200 + lane * 10 + te] += 0.5f * w * expf(-25.f * dm * dm);
                }
            }
        }

        if (lane == 0) {
            x[300] = c_zidx[t0];
            x[301 + t0] = 1.f;
            x[311] = c_zidx[t1];
            x[312 + t1] = 1.f;
        }
        __syncwarp();

        dense_ln_relu_warp(sm + OFF_W1, sm + OFF_B1, sm + OFF_G1, sm + OFF_BE1, x, FEAT, lane);
        dense_ln_relu_warp(sm + OFF_W2, sm + OFF_B2, sm + OFF_G2, sm + OFF_BE2, x, 64, lane);
        dense_ln_relu_warp(sm + OFF_W3, sm + OFF_B3, sm + OFF_G3, sm + OFF_BE3, x, 64, lane);

        float v = x[lane] * sm[OFF_WO + lane] + x[lane + 32] * sm[OFF_WO + lane + 32];
        v = warp_allreduce(v);
        if (lane == 0) {
            atomicAdd(&g_sum, (double)((v + sm[OFF_BO]) * w));
        }
    }
}

// ---------------- kernel 4: writeback ----------------
__global__ void k_final(float* __restrict__ out) {
    if (threadIdx.x == 0) out[0] = (float)g_sum;
}

// ---------------- launch ----------------
extern "C" void kernel_launch(void* const* d_in, const int* in_sizes, int n_in,
                              void* d_out, int out_size)
{
    const float* pos   = (const float*)d_in[0];
    const float* box   = (const float*)d_in[1];
    const float* valid = (const float*)d_in[2];
    const float* W1 = (const float*)d_in[3];
    const float* b1 = (const float*)d_in[4];
    const float* g1 = (const float*)d_in[5];
    const float* be1 = (const float*)d_in[6];
    const float* W2 = (const float*)d_in[7];
    const float* b2 = (const float*)d_in[8];
    const float* g2 = (const float*)d_in[9];
    const float* be2 = (const float*)d_in[10];
    const float* W3 = (const float*)d_in[11];
    const float* b3 = (const float*)d_in[12];
    const float* g3 = (const float*)d_in[13];
    const float* be3 = (const float*)d_in[14];
    const float* Wo = (const float*)d_in[15];
    const float* bo = (const float*)d_in[16];
    const int* pairs = (const int*)d_in[17];
    const int* topo  = (const int*)d_in[18];
    // d_in[19] = topo_mask: redundant (== topo_nblist != -1), unused
    const int* molid = (const int*)d_in[20];
    const int* atype = (const int*)d_in[21];

    int npairs = in_sizes[17] / 3;
    if (npairs > NPAIRS_MAX) npairs = NPAIRS_MAX;

    cudaFuncSetAttribute(k_mlp, cudaFuncAttributeMaxDynamicSharedMemorySize, SMEM_BYTES);

    k_setup<<<1, 32>>>(box);
    k_filter<<<(npairs + 255) / 256, 256>>>(pos, valid, pairs, molid, npairs);
    k_mlp<<<MLP_BLOCKS, NWARPS * 32, SMEM_BYTES>>>(pos, topo, atype,
        W1, b1, g1, be1, W2, b2, g2, be2, W3, b3, g3, be3, Wo, bo);
    k_final<<<1, 32>>>((float*)d_out);
}

// round 3
// speedup vs baseline: 1.5602x; 1.5602x over previous
#include <cuda_runtime.h>
#include <math.h>
#include <stdint.h>

// ---------------- problem constants ----------------
#define NPAIRS_MAX 200000
#define MAX_NB 6
#define NWARPS 8
#define MLP_BLOCKS 148
#define PI_F 3.14159265358979323846f

// feature rows: [0,200) ACSF (k*10+t), [200,300) APSF (k*10+t),
// [300] Zj, [301,311) onehot j, [311] Zk, [312,322) onehot k
#define FEAT 322
#define XROWS 328              // padded rows; each row is a float4 (4 pair slots)

// shared offsets (floats)
#define OFF_W1   0
#define OFF_W2   20608
#define OFF_W3   24704
#define OFF_WO   28800
#define OFF_B1   28864
#define OFF_G1   28928
#define OFF_BE1  28992
#define OFF_B2   29056
#define OFF_G2   29120
#define OFF_BE2  29184
#define OFF_B3   29248
#define OFF_G3   29312
#define OFF_BE3  29376
#define OFF_BO   29440
#define OFF_X    29444                              // 16B aligned
#define SMEM_FLOATS (OFF_X + NWARPS * XROWS * 4)    // 39940
#define SMEM_BYTES  (SMEM_FLOATS * 4)               // 159760

// ---------------- device globals ----------------
__device__ int    g_count;
__device__ int    g_done;
__device__ double g_sum;
__device__ int    g_p0[NPAIRS_MAX];
__device__ int    g_p1[NPAIRS_MAX];
__device__ float4 g_rec[NPAIRS_MAX];   // rij.x, rij.y, rij.z, w

__constant__ float c_zidx[10] = {1.f, 3.f, 5.f, 6.f, 7.f, 8.f, 9.f, 11.f, 15.f, 16.f};

// ---------------- helpers ----------------
__device__ __forceinline__ void box_inverse(const float* b, float* bi) {
    float det = b[0] * (b[4] * b[8] - b[5] * b[7])
              - b[1] * (b[3] * b[8] - b[5] * b[6])
              + b[2] * (b[3] * b[7] - b[4] * b[6]);
    float id = 1.f / det;
    bi[0] = (b[4] * b[8] - b[5] * b[7]) * id;
    bi[1] = (b[2] * b[7] - b[1] * b[8]) * id;
    bi[2] = (b[1] * b[5] - b[2] * b[4]) * id;
    bi[3] = (b[5] * b[6] - b[3] * b[8]) * id;
    bi[4] = (b[0] * b[8] - b[2] * b[6]) * id;
    bi[5] = (b[2] * b[3] - b[0] * b[5]) * id;
    bi[6] = (b[3] * b[7] - b[4] * b[6]) * id;
    bi[7] = (b[1] * b[6] - b[0] * b[7]) * id;
    bi[8] = (b[0] * b[4] - b[1] * b[3]) * id;
}

__device__ __forceinline__ float3 pbc3(float dx, float dy, float dz,
                                       const float* B, const float* Bi) {
    float s0 = dx * Bi[0] + dy * Bi[3] + dz * Bi[6];
    float s1 = dx * Bi[1] + dy * Bi[4] + dz * Bi[7];
    float s2 = dx * Bi[2] + dy * Bi[5] + dz * Bi[8];
    s0 -= floorf(s0 + 0.5f);
    s1 -= floorf(s1 + 0.5f);
    s2 -= floorf(s2 + 0.5f);
    float3 r;
    r.x = s0 * B[0] + s1 * B[3] + s2 * B[6];
    r.y = s0 * B[1] + s1 * B[4] + s2 * B[7];
    r.z = s0 * B[2] + s1 * B[5] + s2 * B[8];
    return r;
}

__device__ __forceinline__ float4 allreduce4(float4 v) {
#pragma unroll
    for (int o = 16; o > 0; o >>= 1) {
        v.x += __shfl_xor_sync(0xffffffffu, v.x, o);
        v.y += __shfl_xor_sync(0xffffffffu, v.y, o);
        v.z += __shfl_xor_sync(0xffffffffu, v.z, o);
        v.w += __shfl_xor_sync(0xffffffffu, v.w, o);
    }
    return v;
}

// 4 pair-slots per warp: x rows are float4. h = x@W + b ; LN ; relu ; back to x.
__device__ __forceinline__ void dense4(
    const float* __restrict__ Ws, const float* __restrict__ bb,
    const float* __restrict__ gg, const float* __restrict__ be,
    float* x, int inDim, int lane)
{
    float b0 = bb[lane], b1 = bb[lane + 32];
    float4 a0 = make_float4(b0, b0, b0, b0);
    float4 a1 = make_float4(b1, b1, b1, b1);
    const float* w0p = Ws + lane;
    const float* w1p = Ws + lane + 32;
#pragma unroll 4
    for (int i = 0; i < inDim; i++) {
        float4 xv = *(const float4*)(x + i * 4);
        float w0 = w0p[i * 64];
        float w1 = w1p[i * 64];
        a0.x = fmaf(xv.x, w0, a0.x); a0.y = fmaf(xv.y, w0, a0.y);
        a0.z = fmaf(xv.z, w0, a0.z); a0.w = fmaf(xv.w, w0, a0.w);
        a1.x = fmaf(xv.x, w1, a1.x); a1.y = fmaf(xv.y, w1, a1.y);
        a1.z = fmaf(xv.z, w1, a1.z); a1.w = fmaf(xv.w, w1, a1.w);
    }
    float4 s = make_float4(a0.x + a1.x, a0.y + a1.y, a0.z + a1.z, a0.w + a1.w);
    s = allreduce4(s);
    float4 mu = make_float4(s.x * (1.f/64.f), s.y * (1.f/64.f), s.z * (1.f/64.f), s.w * (1.f/64.f));
    float4 d0 = make_float4(a0.x - mu.x, a0.y - mu.y, a0.z - mu.z, a0.w - mu.w);
    float4 d1 = make_float4(a1.x - mu.x, a1.y - mu.y, a1.z - mu.z, a1.w - mu.w);
    float4 v = make_float4(d0.x*d0.x + d1.x*d1.x, d0.y*d0.y + d1.y*d1.y,
                           d0.z*d0.z + d1.z*d1.z, d0.w*d0.w + d1.w*d1.w);
    v = allreduce4(v);
    float4 r = make_float4(rsqrtf(v.x * (1.f/64.f) + 1e-6f),
                           rsqrtf(v.y * (1.f/64.f) + 1e-6f),
                           rsqrtf(v.z * (1.f/64.f) + 1e-6f),
                           rsqrtf(v.w * (1.f/64.f) + 1e-6f));
    float g0 = gg[lane], g1 = gg[lane + 32];
    float e0 = be[lane], e1 = be[lane + 32];
    float4 y0 = make_float4(fmaxf(d0.x * r.x * g0 + e0, 0.f),
                            fmaxf(d0.y * r.y * g0 + e0, 0.f),
                            fmaxf(d0.z * r.z * g0 + e0, 0.f),
                            fmaxf(d0.w * r.w * g0 + e0, 0.f));
    float4 y1 = make_float4(fmaxf(d1.x * r.x * g1 + e1, 0.f),
                            fmaxf(d1.y * r.y * g1 + e1, 0.f),
                            fmaxf(d1.z * r.z * g1 + e1, 0.f),
                            fmaxf(d1.w * r.w * g1 + e1, 0.f));
    __syncwarp();
    *(float4*)(x + lane * 4) = y0;
    *(float4*)(x + (lane + 32) * 4) = y1;
    __syncwarp();
}

// ---------------- kernel 1: filter + compact ----------------
__global__ void k_filter(const float* __restrict__ pos,
                         const float* __restrict__ box,
                         const float* __restrict__ valid,
                         const int* __restrict__ pairs,
                         const int* __restrict__ molid,
                         int npairs)
{
    int i = blockIdx.x * blockDim.x + threadIdx.x;
    if (i >= npairs) return;
    int p0 = pairs[3 * i];
    int p1 = pairs[3 * i + 1];
    if (p1 - p0 <= 0) { p0 -= 1; p1 -= 2; }
    if (p0 >= p1) return;
    if (molid[p0] == molid[p1]) return;
    float bs = valid[i];
    if (bs == 0.f) return;

    float B[9], Bi[9];
#pragma unroll
    for (int k = 0; k < 9; k++) B[k] = box[k];
    box_inverse(B, Bi);

    float ax = pos[3 * p0], ay = pos[3 * p0 + 1], az = pos[3 * p0 + 2];
    float bx = pos[3 * p1], by = pos[3 * p1 + 1], bz = pos[3 * p1 + 2];
    float3 r = pbc3(bx - ax, by - ay, bz - az, B, Bi);
    float cx = r.x + 1e-10f, cy = r.y + 1e-10f, cz = r.z + 1e-10f;
    float dn = sqrtf(cx * cx + cy * cy + cz * cz);
    if (dn > 5.0f) return;
    float cut = 0.5f * (1.f + cosf(PI_F * dn * (1.f / 5.f)));
    float w = bs * cut;
    if (w <= 0.f) return;

    int slot = atomicAdd(&g_count, 1);
    g_p0[slot] = p0;
    g_p1[slot] = p1;
    g_rec[slot] = make_float4(r.x, r.y, r.z, w);
}

// ---------------- kernel 2: features + MLP, 4 pairs per warp; last block finalizes ----------------
__global__ __launch_bounds__(NWARPS * 32, 1)
void k_mlp(const float* __restrict__ pos,
           const float* __restrict__ box,
           const int* __restrict__ topo,
           const int* __restrict__ atype,
           const float* __restrict__ W1, const float* __restrict__ b1,
           const float* __restrict__ g1, const float* __restrict__ be1,
           const float* __restrict__ W2, const float* __restrict__ b2,
           const float* __restrict__ g2, const float* __restrict__ be2,
           const float* __restrict__ W3, const float* __restrict__ b3,
           const float* __restrict__ g3, const float* __restrict__ be3,
           const float* __restrict__ Wo, const float* __restrict__ bo,
           float* __restrict__ out)
{
    extern __shared__ float sm[];
    int tid = threadIdx.x;

    // stage weights (float4 copies)
    {
        const float4* W1v = (const float4*)W1;
        float4* s1 = (float4*)(sm + OFF_W1);
        for (int i = tid; i < 20608 / 4; i += NWARPS * 32) s1[i] = W1v[i];
        const float4* W2v = (const float4*)W2;
        const float4* W3v = (const float4*)W3;
        float4* s2 = (float4*)(sm + OFF_W2);
        float4* s3 = (float4*)(sm + OFF_W3);
        for (int i = tid; i < 1024; i += NWARPS * 32) { s2[i] = W2v[i]; s3[i] = W3v[i]; }
        if (tid < 64) {
            sm[OFF_WO + tid] = Wo[tid];
            sm[OFF_B1 + tid] = b1[tid]; sm[OFF_G1 + tid] = g1[tid]; sm[OFF_BE1 + tid] = be1[tid];
            sm[OFF_B2 + tid] = b2[tid]; sm[OFF_G2 + tid] = g2[tid]; sm[OFF_BE2 + tid] = be2[tid];
            sm[OFF_B3 + tid] = b3[tid]; sm[OFF_G3 + tid] = g3[tid]; sm[OFF_BE3 + tid] = be3[tid];
        }
        if (tid == 0) sm[OFF_BO] = bo[0];
    }
    __syncthreads();

    float B[9], Bi[9];
#pragma unroll
    for (int k = 0; k < 9; k++) B[k] = box[k];
    box_inverse(B, Bi);

    int lane = tid & 31;
    int wid = tid >> 5;
    float* x = sm + OFF_X + wid * (XROWS * 4);
    int n = g_count;
    int ngroups = (n + 3) >> 2;

    for (int grp = blockIdx.x * NWARPS + wid; grp < ngroups; grp += MLP_BLOCKS * NWARPS) {
        int base = grp * 4;
        int np = n - base; if (np > 4) np = 4;

        // per-slot metadata (uniform loads)
        int p0s[4], p1s[4];
        float uxs[4], uys[4], uzs[4], ws[4];
#pragma unroll
        for (int s = 0; s < 4; s++) {
            if (s < np) {
                p0s[s] = g_p0[base + s];
                p1s[s] = g_p1[base + s];
                float4 rc = g_rec[base + s];
                float cx = rc.x + 1e-10f, cy = rc.y + 1e-10f, cz = rc.z + 1e-10f;
                float dn = sqrtf(cx * cx + cy * cy + cz * cz);
                float ui = 1.f / (dn + 1e-10f);
                uxs[s] = rc.x * ui; uys[s] = rc.y * ui; uzs[s] = rc.z * ui;
                ws[s] = rc.w;
            } else { p0s[s] = 0; p1s[s] = 0; uxs[s] = uys[s] = uzs[s] = 0.f; ws[s] = 0.f; }
        }

        // zero feature rows
        {
            float4 z = make_float4(0.f, 0.f, 0.f, 0.f);
            float4* xv = (float4*)x;
            for (int i = lane; i < XROWS; i += 32) xv[i] = z;
        }
        __syncwarp();

        // parallel gather: lanes 0..23 fetch neighbors for slots {0,1} (set A) and
        // {2,3} (set B); lanes 24..31 fetch the 8 pair-atom centers.
        int nbA = -1, tA = 0, nbB = -1, tB = 0;
        float xA = 0.f, yA = 0.f, zA = 0.f, xB = 0.f, yB = 0.f, zB = 0.f;
        float cpx = 0.f, cpy = 0.f, cpz = 0.f; int cpt = 0;
        if (lane < 24) {
            int pr = lane / 12;
            int e = lane % 12;
            int side = e / 6, m = e % 6;
            if (pr < np) {
                int a = side ? p1s[pr] : p0s[pr];
                nbA = topo[a * MAX_NB + m];
            }
            int prB = pr + 2;
            if (prB < np) {
                int a = side ? p1s[prB] : p0s[prB];
                nbB = topo[a * MAX_NB + m];
            }
        } else {
            int k = lane - 24;
            int slot = k >> 1, which = k & 1;
            if (slot < np) {
                int a = which ? p1s[slot] : p0s[slot];
                cpx = pos[3 * a]; cpy = pos[3 * a + 1]; cpz = pos[3 * a + 2];
                cpt = atype[a];
            }
        }
        if (lane < 24) {
            if (nbA >= 0) { xA = pos[3 * nbA]; yA = pos[3 * nbA + 1]; zA = pos[3 * nbA + 2]; tA = atype[nbA]; }
            if (nbB >= 0) { xB = pos[3 * nbB]; yB = pos[3 * nbB + 1]; zB = pos[3 * nbB + 2]; tB = atype[nbB]; }
        }
        __syncwarp();

        // contribution loop
#pragma unroll
        for (int slot = 0; slot < 4; slot++) {
            if (slot >= np) break;
            int t0 = __shfl_sync(0xffffffffu, cpt, 24 + slot * 2);
            int t1 = __shfl_sync(0xffffffffu, cpt, 25 + slot * 2);
            float c0x = __shfl_sync(0xffffffffu, cpx, 24 + slot * 2);
            float c0y = __shfl_sync(0xffffffffu, cpy, 24 + slot * 2);
            float c0z = __shfl_sync(0xffffffffu, cpz, 24 + slot * 2);
            float c1x = __shfl_sync(0xffffffffu, cpx, 25 + slot * 2);
            float c1y = __shfl_sync(0xffffffffu, cpy, 25 + slot * 2);
            float c1z = __shfl_sync(0xffffffffu, cpz, 25 + slot * 2);
            float ux = uxs[slot], uy = uys[slot], uz = uzs[slot];
            float cw = ws[slot];
            int q0 = p0s[slot], q1 = p1s[slot];

            if (lane == 0) {
                x[300 * 4 + slot] = c_zidx[t0];
                x[(301 + t0) * 4 + slot] = 1.f;
                x[311 * 4 + slot] = c_zidx[t1];
                x[(312 + t1) * 4 + slot] = 1.f;
            }

            for (int e = 0; e < 12; e++) {
                int srcLane = (slot & 1) * 12 + e;
                int nbe, te; float ex, ey, ez;
                if (slot < 2) {
                    nbe = __shfl_sync(0xffffffffu, nbA, srcLane);
                    ex = __shfl_sync(0xffffffffu, xA, srcLane);
                    ey = __shfl_sync(0xffffffffu, yA, srcLane);
                    ez = __shfl_sync(0xffffffffu, zA, srcLane);
                    te = __shfl_sync(0xffffffffu, tA, srcLane);
                } else {
                    nbe = __shfl_sync(0xffffffffu, nbB, srcLane);
                    ex = __shfl_sync(0xffffffffu, xB, srcLane);
                    ey = __shfl_sync(0xffffffffu, yB, srcLane);
                    ez = __shfl_sync(0xffffffffu, zB, srcLane);
                    te = __shfl_sync(0xffffffffu, tB, srcLane);
                }
                if (nbe < 0) continue;
                int side = e / 6;
                float cx = side ? c1x : c0x;
                float cy = side ? c1y : c0y;
                float cz = side ? c1z : c0z;
                float3 d = pbc3(ex - cx, ey - cy, ez - cz, B, Bi);
                float ddx = d.x + 1e-10f, ddy = d.y + 1e-10f, ddz = d.z + 1e-10f;
                float edn = sqrtf(ddx * ddx + ddy * ddy + ddz * ddz);

                float fx = edn * 0.2f;
                if (fx < 1.f) {
                    float fc = 0.5f * (cosf(PI_F * fx) + 1.f);
                    if (lane < 20) {
                        float dm = edn - (float)lane * (5.f / 19.f);
                        x[(lane * 10 + te) * 4 + slot] += 0.5f * fc * expf(-100.f * dm * dm);
                    }
                }
                if (nbe != q0 && nbe != q1) {
                    float idn = 1.f / edn;
                    float sgn = side ? -1.f : 1.f;
                    float cg = (d.x * ux + d.y * uy + d.z * uz) * idn * sgn;
                    if (lane < 10) {
                        float dm = cg - (-1.f + (float)lane * (2.f / 9.f));
                        x[(200 + lane * 10 + te) * 4 + slot] += 0.5f * cw * expf(-25.f * dm * dm);
                    }
                }
            }
        }
        __syncwarp();

        dense4(sm + OFF_W1, sm + OFF_B1, sm + OFF_G1, sm + OFF_BE1, x, FEAT, lane);
        dense4(sm + OFF_W2, sm + OFF_B2, sm + OFF_G2, sm + OFF_BE2, x, 64, lane);
        dense4(sm + OFF_W3, sm + OFF_B3, sm + OFF_G3, sm + OFF_BE3, x, 64, lane);

        float wo0 = sm[OFF_WO + lane], wo1 = sm[OFF_WO + lane + 32];
        float4 xv0 = *(const float4*)(x + lane * 4);
        float4 xv1 = *(const float4*)(x + (lane + 32) * 4);
        float4 v = make_float4(xv0.x * wo0 + xv1.x * wo1,
                               xv0.y * wo0 + xv1.y * wo1,
                               xv0.z * wo0 + xv1.z * wo1,
                               xv0.w * wo0 + xv1.w * wo1);
        v = allreduce4(v);
        if (lane == 0) {
            float bov = sm[OFF_BO];
            float tot = (v.x + bov) * ws[0] + (v.y + bov) * ws[1]
                      + (v.z + bov) * ws[2] + (v.w + bov) * ws[3];
            atomicAdd(&g_sum, (double)tot);
        }
    }

    // finalize: last block to finish writes output and resets state for next replay
    __syncthreads();
    if (tid == 0) {
        __threadfence();
        int done = atomicAdd(&g_done, 1);
        if (done == MLP_BLOCKS - 1) {
            double s = atomicAdd(&g_sum, 0.0);   // coherent read
            out[0] = (float)s;
            g_sum = 0.0;
            g_count = 0;
            g_done = 0;
        }
    }
}

// ---------------- launch ----------------
extern "C" void kernel_launch(void* const* d_in, const int* in_sizes, int n_in,
                              void* d_out, int out_size)
{
    const float* pos   = (const float*)d_in[0];
    const float* box   = (const float*)d_in[1];
    const float* valid = (const float*)d_in[2];
    const float* W1 = (const float*)d_in[3];
    const float* b1 = (const float*)d_in[4];
    const float* g1 = (const float*)d_in[5];
    const float* be1 = (const float*)d_in[6];
    const float* W2 = (const float*)d_in[7];
    const float* b2 = (const float*)d_in[8];
    const float* g2 = (const float*)d_in[9];
    const float* be2 = (const float*)d_in[10];
    const float* W3 = (const float*)d_in[11];
    const float* b3 = (const float*)d_in[12];
    const float* g3 = (const float*)d_in[13];
    const float* be3 = (const float*)d_in[14];
    const float* Wo = (const float*)d_in[15];
    const float* bo = (const float*)d_in[16];
    const int* pairs = (const int*)d_in[17];
    const int* topo  = (const int*)d_in[18];
    // d_in[19] topo_mask: redundant with topo != -1
    const int* molid = (const int*)d_in[20];
    const int* atype = (const int*)d_in[21];

    int npairs = in_sizes[17] / 3;
    if (npairs > NPAIRS_MAX) npairs = NPAIRS_MAX;

    cudaFuncSetAttribute(k_mlp, cudaFuncAttributeMaxDynamicSharedMemorySize, SMEM_BYTES);

    k_filter<<<(npairs + 255) / 256, 256>>>(pos, box, valid, pairs, molid, npairs);
    k_mlp<<<MLP_BLOCKS, NWARPS * 32, SMEM_BYTES>>>(pos, box, topo, atype,
        W1, b1, g1, be1, W2, b2, g2, be2, W3, b3, g3, be3, Wo, bo,
        (float*)d_out);
}

// round 4
// speedup vs baseline: 1.6369x; 1.0492x over previous
#include <cuda_runtime.h>
#include <math.h>
#include <stdint.h>

// ---------------- problem constants ----------------
#define NPAIRS_MAX 200000
#define MAX_NB 6
#define NWARPS 16
#define THREADS (NWARPS * 32)
#define MLP_BLOCKS 148
#define PI_F 3.14159265358979323846f

// feature rows: [0,200) ACSF (k*10+t), [200,300) APSF (k*10+t),
// [300] Zj, [301,311) onehot j, [311] Zk, [312,322) onehot k
#define FEAT 322
#define XROWS 328              // padded rows; each row is float2 (2 pair slots)

// shared layout (floats): W1 interleaved [i*64 + pos], then per-warp x buffers
#define W1_FLOATS 20608        // 322*64
#define OFF_X     W1_FLOATS
#define SMEM_FLOATS (OFF_X + NWARPS * XROWS * 2)   // 20608 + 10496 = 31104
#define SMEM_BYTES  (SMEM_FLOATS * 4)              // 124416

// ---------------- device globals ----------------
__device__ int    g_count;
__device__ int    g_done;
__device__ double g_sum;
__device__ int    g_p0[NPAIRS_MAX];
__device__ int    g_p1[NPAIRS_MAX];
__device__ float4 g_rec[NPAIRS_MAX];   // rij.x, rij.y, rij.z, w

__constant__ float c_zidx[10] = {1.f, 3.f, 5.f, 6.f, 9.f, 8.f, 9.f, 11.f, 15.f, 16.f};
// NOTE: table re-verified below (typo guard): correct values set in c_zidx2
__constant__ float c_zidx2[10] = {1.f, 3.f, 5.f, 6.f, 7.f, 8.f, 9.f, 11.f, 15.f, 16.f};

// ---------------- helpers ----------------
__device__ __forceinline__ void box_inverse(const float* b, float* bi) {
    float det = b[0] * (b[4] * b[8] - b[5] * b[7])
              - b[1] * (b[3] * b[8] - b[5] * b[6])
              + b[2] * (b[3] * b[7] - b[4] * b[6]);
    float id = 1.f / det;
    bi[0] = (b[4] * b[8] - b[5] * b[7]) * id;
    bi[1] = (b[2] * b[7] - b[1] * b[8]) * id;
    bi[2] = (b[1] * b[5] - b[2] * b[4]) * id;
    bi[3] = (b[5] * b[6] - b[3] * b[8]) * id;
    bi[4] = (b[0] * b[8] - b[2] * b[6]) * id;
    bi[5] = (b[2] * b[3] - b[0] * b[5]) * id;
    bi[6] = (b[3] * b[7] - b[4] * b[6]) * id;
    bi[7] = (b[1] * b[6] - b[0] * b[7]) * id;
    bi[8] = (b[0] * b[4] - b[1] * b[3]) * id;
}

__device__ __forceinline__ float3 pbc3(float dx, float dy, float dz,
                                       const float* B, const float* Bi) {
    float s0 = dx * Bi[0] + dy * Bi[3] + dz * Bi[6];
    float s1 = dx * Bi[1] + dy * Bi[4] + dz * Bi[7];
    float s2 = dx * Bi[2] + dy * Bi[5] + dz * Bi[8];
    s0 -= floorf(s0 + 0.5f);
    s1 -= floorf(s1 + 0.5f);
    s2 -= floorf(s2 + 0.5f);
    float3 r;
    r.x = s0 * B[0] + s1 * B[3] + s2 * B[6];
    r.y = s0 * B[1] + s1 * B[4] + s2 * B[7];
    r.z = s0 * B[2] + s1 * B[5] + s2 * B[8];
    return r;
}

__device__ __forceinline__ float2 allreduce2(float2 v) {
#pragma unroll
    for (int o = 16; o > 0; o >>= 1) {
        v.x += __shfl_xor_sync(0xffffffffu, v.x, o);
        v.y += __shfl_xor_sync(0xffffffffu, v.y, o);
    }
    return v;
}

// LayerNorm+ReLU on 64 outputs held as (a0 = out lane, a1 = out lane+32), 2 slots.
__device__ __forceinline__ void ln_relu2(
    float2& a0, float2& a1,
    const float* __restrict__ gg, const float* __restrict__ be, int lane)
{
    float2 s = make_float2(a0.x + a1.x, a0.y + a1.y);
    s = allreduce2(s);
    float2 mu = make_float2(s.x * (1.f/64.f), s.y * (1.f/64.f));
    float2 d0 = make_float2(a0.x - mu.x, a0.y - mu.y);
    float2 d1 = make_float2(a1.x - mu.x, a1.y - mu.y);
    float2 v = make_float2(d0.x*d0.x + d1.x*d1.x, d0.y*d0.y + d1.y*d1.y);
    v = allreduce2(v);
    float2 r = make_float2(rsqrtf(v.x * (1.f/64.f) + 1e-6f),
                           rsqrtf(v.y * (1.f/64.f) + 1e-6f));
    float g0 = __ldg(gg + lane), g1 = __ldg(gg + lane + 32);
    float e0 = __ldg(be + lane), e1 = __ldg(be + lane + 32);
    a0 = make_float2(fmaxf(d0.x * r.x * g0 + e0, 0.f),
                     fmaxf(d0.y * r.y * g0 + e0, 0.f));
    a1 = make_float2(fmaxf(d1.x * r.x * g1 + e1, 0.f),
                     fmaxf(d1.y * r.y * g1 + e1, 0.f));
}

// dense 64->64 with input in registers (y0 = in lane, y1 = in lane+32; 2 slots),
// weights from global via __ldg (L1-resident after warmup).
__device__ __forceinline__ void dense_reg(
    const float* __restrict__ Wg, const float* __restrict__ bb,
    const float* __restrict__ gg, const float* __restrict__ be,
    float2& y0, float2& y1, int lane)
{
    float b0 = __ldg(bb + lane), b1 = __ldg(bb + lane + 32);
    float2 a0 = make_float2(b0, b0);
    float2 a1 = make_float2(b1, b1);
#pragma unroll 8
    for (int i = 0; i < 32; i++) {
        float xs0 = __shfl_sync(0xffffffffu, y0.x, i);
        float xs1 = __shfl_sync(0xffffffffu, y0.y, i);
        float w0 = __ldg(Wg + i * 64 + lane);
        float w1 = __ldg(Wg + i * 64 + lane + 32);
        a0.x = fmaf(xs0, w0, a0.x); a0.y = fmaf(xs1, w0, a0.y);
        a1.x = fmaf(xs0, w1, a1.x); a1.y = fmaf(xs1, w1, a1.y);
    }
#pragma unroll 8
    for (int i = 0; i < 32; i++) {
        float xs0 = __shfl_sync(0xffffffffu, y1.x, i);
        float xs1 = __shfl_sync(0xffffffffu, y1.y, i);
        float w0 = __ldg(Wg + (i + 32) * 64 + lane);
        float w1 = __ldg(Wg + (i + 32) * 64 + lane + 32);
        a0.x = fmaf(xs0, w0, a0.x); a0.y = fmaf(xs1, w0, a0.y);
        a1.x = fmaf(xs0, w1, a1.x); a1.y = fmaf(xs1, w1, a1.y);
    }
    ln_relu2(a0, a1, gg, be, lane);
    y0 = a0; y1 = a1;
}

// ---------------- kernel 1: filter + compact ----------------
__global__ void k_filter(const float* __restrict__ pos,
                         const float* __restrict__ box,
                         const float* __restrict__ valid,
                         const int* __restrict__ pairs,
                         const int* __restrict__ molid,
                         int npairs)
{
    int i = blockIdx.x * blockDim.x + threadIdx.x;
    if (i >= npairs) return;
    int p0 = pairs[3 * i];
    int p1 = pairs[3 * i + 1];
    if (p1 - p0 <= 0) { p0 -= 1; p1 -= 2; }
    if (p0 >= p1) return;
    if (__ldg(molid + p0) == __ldg(molid + p1)) return;
    float bs = __ldg(valid + i);
    if (bs == 0.f) return;

    float B[9], Bi[9];
#pragma unroll
    for (int k = 0; k < 9; k++) B[k] = box[k];
    box_inverse(B, Bi);

    float ax = __ldg(pos + 3 * p0), ay = __ldg(pos + 3 * p0 + 1), az = __ldg(pos + 3 * p0 + 2);
    float bx = __ldg(pos + 3 * p1), by = __ldg(pos + 3 * p1 + 1), bz = __ldg(pos + 3 * p1 + 2);
    float3 r = pbc3(bx - ax, by - ay, bz - az, B, Bi);
    float cx = r.x + 1e-10f, cy = r.y + 1e-10f, cz = r.z + 1e-10f;
    float dn = sqrtf(cx * cx + cy * cy + cz * cz);
    if (dn > 5.0f) return;
    float cut = 0.5f * (1.f + __cosf(PI_F * dn * (1.f / 5.f)));
    float w = bs * cut;
    if (w <= 0.f) return;

    int slot = atomicAdd(&g_count, 1);
    g_p0[slot] = p0;
    g_p1[slot] = p1;
    g_rec[slot] = make_float4(r.x, r.y, r.z, w);
}

// ---------------- kernel 2: features + MLP, 2 pairs per warp ----------------
__global__ __launch_bounds__(THREADS, 1)
void k_mlp(const float* __restrict__ pos,
           const float* __restrict__ box,
           const int* __restrict__ topo,
           const int* __restrict__ atype,
           const float* __restrict__ W1, const float* __restrict__ b1,
           const float* __restrict__ g1, const float* __restrict__ be1,
           const float* __restrict__ W2, const float* __restrict__ b2,
           const float* __restrict__ g2, const float* __restrict__ be2,
           const float* __restrict__ W3, const float* __restrict__ b3,
           const float* __restrict__ g3, const float* __restrict__ be3,
           const float* __restrict__ Wo, const float* __restrict__ bo,
           float* __restrict__ out)
{
    extern __shared__ float sm[];
    int tid = threadIdx.x;

    // stage W1 interleaved: sm[i*64 + 2*o] = W1[i][o], sm[i*64 + 2*o+1] = W1[i][o+32]
    for (int idx = tid; idx < W1_FLOATS; idx += THREADS) {
        int i = idx >> 6, o = idx & 63;
        int p = (o < 32) ? (o * 2) : ((o - 32) * 2 + 1);
        sm[(i << 6) + p] = __ldg(W1 + idx);
    }
    __syncthreads();

    float B[9], Bi[9];
#pragma unroll
    for (int k = 0; k < 9; k++) B[k] = box[k];
    box_inverse(B, Bi);

    int lane = tid & 31;
    int wid = tid >> 5;
    float* x = sm + OFF_X + wid * (XROWS * 2);
    int n = g_count;
    int ngroups = (n + 1) >> 1;

    float mu_acsf = (float)lane * (5.f / 19.f);           // lanes 0..19
    float mu_apsf = -1.f + (float)(lane - 20) * (2.f / 9.f); // lanes 20..29

    for (int grp = wid * gridDim.x + blockIdx.x; grp < ngroups;
         grp += gridDim.x * NWARPS) {
        int base = grp * 2;
        int np = n - base; if (np > 2) np = 2;

        int q0s[2], q1s[2];
        float uxs[2], uys[2], uzs[2], wss[2];
#pragma unroll
        for (int s = 0; s < 2; s++) {
            if (s < np) {
                q0s[s] = g_p0[base + s];
                q1s[s] = g_p1[base + s];
                float4 rc = g_rec[base + s];
                float cx = rc.x + 1e-10f, cy = rc.y + 1e-10f, cz = rc.z + 1e-10f;
                float dn = sqrtf(cx * cx + cy * cy + cz * cz);
                float ui = 1.f / (dn + 1e-10f);
                uxs[s] = rc.x * ui; uys[s] = rc.y * ui; uzs[s] = rc.z * ui;
                wss[s] = rc.w;
            } else { q0s[s] = 0; q1s[s] = 0; uxs[s] = uys[s] = uzs[s] = 0.f; wss[s] = 0.f; }
        }

        // zero feature rows (656 floats = 164 float4)
        {
            float4 z = make_float4(0.f, 0.f, 0.f, 0.f);
            float4* xv = (float4*)x;
#pragma unroll
            for (int i = lane; i < XROWS * 2 / 4; i += 32) xv[i] = z;
        }
        __syncwarp();

        // gathers: lanes 0..23 -> neighbors (slot=lane/12, side=(lane%12)/6, m=lane%6),
        // lanes 24..27 -> pair-atom centers (slot=(lane-24)/2, which=(lane-24)&1)
        int nbL = -1, tL = 0;
        float nxL = 0.f, nyL = 0.f, nzL = 0.f;
        float cpx = 0.f, cpy = 0.f, cpz = 0.f; int cpt = 0;
        if (lane < 24) {
            int sl = lane / 12;
            int e = lane % 12;
            int side = e / 6, m = e % 6;
            int a = side ? q1s[sl] : q0s[sl];
            nbL = __ldg(topo + a * MAX_NB + m);
            if (nbL >= 0) {
                nxL = __ldg(pos + 3 * nbL);
                nyL = __ldg(pos + 3 * nbL + 1);
                nzL = __ldg(pos + 3 * nbL + 2);
                tL = __ldg(atype + nbL);
            }
        } else if (lane < 28) {
            int k = lane - 24;
            int sl = k >> 1, which = k & 1;
            int a = which ? q1s[sl] : q0s[sl];
            cpx = __ldg(pos + 3 * a); cpy = __ldg(pos + 3 * a + 1); cpz = __ldg(pos + 3 * a + 2);
            cpt = __ldg(atype + a);
        }
        __syncwarp();

        // element/onehot block: lane s (0/1) fills slot s
        {
            int t0v = __shfl_sync(0xffffffffu, cpt, 24 + (lane & 1) * 2);
            int t1v = __shfl_sync(0xffffffffu, cpt, 25 + (lane & 1) * 2);
            if (lane < 2) {
                x[300 * 2 + lane] = c_zidx2[t0v];
                x[(301 + t0v) * 2 + lane] = 1.f;
                x[311 * 2 + lane] = c_zidx2[t1v];
                x[(312 + t1v) * 2 + lane] = 1.f;
            }
        }

        // edge loop: 24 edges (12 per slot)
        for (int e = 0; e < 24; e++) {
            int nbe = __shfl_sync(0xffffffffu, nbL, e);
            if (nbe < 0) continue;                      // uniform
            float ex = __shfl_sync(0xffffffffu, nxL, e);
            float ey = __shfl_sync(0xffffffffu, nyL, e);
            float ez = __shfl_sync(0xffffffffu, nzL, e);
            int te = __shfl_sync(0xffffffffu, tL, e);
            int sl = e / 12;
            int side = (e % 12) / 6;
            int srcC = 24 + sl * 2 + side;
            float cx = __shfl_sync(0xffffffffu, cpx, srcC);
            float cy = __shfl_sync(0xffffffffu, cpy, srcC);
            float cz = __shfl_sync(0xffffffffu, cpz, srcC);

            float3 d = pbc3(ex - cx, ey - cy, ez - cz, B, Bi);
            float ddx = d.x + 1e-10f, ddy = d.y + 1e-10f, ddz = d.z + 1e-10f;
            float r2 = ddx * ddx + ddy * ddy + ddz * ddz;
            float rinv = rsqrtf(r2);
            float edn = r2 * rinv;

            if (lane < 20) {
                // ACSF
                float fx = edn * 0.2f;
                if (fx < 1.f) {
                    float fc = 0.5f * (__cosf(PI_F * fx) + 1.f);
                    float dm = edn - mu_acsf;
                    x[(lane * 10 + te) * 2 + sl] += 0.5f * fc * __expf(-100.f * dm * dm);
                }
            } else if (lane < 30) {
                // APSF (exclude the pair atoms)
                if (nbe != q0s[sl] && nbe != q1s[sl]) {
                    float sgn = side ? -1.f : 1.f;
                    float cg = (d.x * uxs[sl] + d.y * uys[sl] + d.z * uzs[sl]) * rinv * sgn;
                    float dm = cg - mu_apsf;
                    x[(200 + (lane - 20) * 10 + te) * 2 + sl] +=
                        0.5f * wss[sl] * __expf(-25.f * dm * dm);
                }
            }
        }
        __syncwarp();

        // dense1: W1 from smem (interleaved), x rows float2
        float2 y0, y1;
        {
            float bb0 = __ldg(b1 + lane), bb1 = __ldg(b1 + lane + 32);
            float2 a0 = make_float2(bb0, bb0);
            float2 a1 = make_float2(bb1, bb1);
            const float2* wp = (const float2*)sm + lane;
#pragma unroll 4
            for (int i = 0; i < FEAT; i++) {
                float2 xv = *(const float2*)(x + 2 * i);
                float2 wv = wp[i * 32];
                a0.x = fmaf(xv.x, wv.x, a0.x); a0.y = fmaf(xv.y, wv.x, a0.y);
                a1.x = fmaf(xv.x, wv.y, a1.x); a1.y = fmaf(xv.y, wv.y, a1.y);
            }
            ln_relu2(a0, a1, g1, be1, lane);
            y0 = a0; y1 = a1;
        }

        dense_reg(W2, b2, g2, be2, y0, y1, lane);
        dense_reg(W3, b3, g3, be3, y0, y1, lane);

        // output layer + weighted accumulation
        float wo0 = __ldg(Wo + lane), wo1 = __ldg(Wo + lane + 32);
        float2 v = make_float2(y0.x * wo0 + y1.x * wo1,
                               y0.y * wo0 + y1.y * wo1);
        v = allreduce2(v);
        if (lane == 0) {
            float bov = __ldg(bo);
            float tot = (v.x + bov) * wss[0] + (v.y + bov) * wss[1];
            atomicAdd(&g_sum, (double)tot);
        }
    }

    // finalize: last block writes output and resets state for next graph replay
    __syncthreads();
    if (tid == 0) {
        __threadfence();
        int done = atomicAdd(&g_done, 1);
        if (done == (int)gridDim.x - 1) {
            double s = atomicAdd(&g_sum, 0.0);   // coherent read
            out[0] = (float)s;
            g_sum = 0.0;
            g_count = 0;
            g_done = 0;
        }
    }
}

// ---------------- launch ----------------
extern "C" void kernel_launch(void* const* d_in, const int* in_sizes, int n_in,
                              void* d_out, int out_size)
{
    const float* pos   = (const float*)d_in[0];
    const float* box   = (const float*)d_in[1];
    const float* valid = (const float*)d_in[2];
    const float* W1 = (const float*)d_in[3];
    const float* b1 = (const float*)d_in[4];
    const float* g1 = (const float*)d_in[5];
    const float* be1 = (const float*)d_in[6];
    const float* W2 = (const float*)d_in[7];
    const float* b2 = (const float*)d_in[8];
    const float* g2 = (const float*)d_in[9];
    const float* be2 = (const float*)d_in[10];
    const float* W3 = (const float*)d_in[11];
    const float* b3 = (const float*)d_in[12];
    const float* g3 = (const float*)d_in[13];
    const float* be3 = (const float*)d_in[14];
    const float* Wo = (const float*)d_in[15];
    const float* bo = (const float*)d_in[16];
    const int* pairs = (const int*)d_in[17];
    const int* topo  = (const int*)d_in[18];
    // d_in[19] topo_mask: redundant with topo != -1
    const int* molid = (const int*)d_in[20];
    const int* atype = (const int*)d_in[21];

    int npairs = in_sizes[17] / 3;
    if (npairs > NPAIRS_MAX) npairs = NPAIRS_MAX;

    cudaFuncSetAttribute(k_mlp, cudaFuncAttributeMaxDynamicSharedMemorySize, SMEM_BYTES);

    k_filter<<<(npairs + 255) / 256, 256>>>(pos, box, valid, pairs, molid, npairs);
    k_mlp<<<MLP_BLOCKS, THREADS, SMEM_BYTES>>>(pos, box, topo, atype,
        W1, b1, g1, be1, W2, b2, g2, be2, W3, b3, g3, be3, Wo, bo,
        (float*)d_out);
}

// round 5
// speedup vs baseline: 1.6409x; 1.0025x over previous
#include <cuda_runtime.h>
#include <math.h>
#include <stdint.h>

// ---------------- problem constants ----------------
#define NPAIRS_MAX 200000
#define MAX_NB 6
#define NWARPS 8
#define THREADS (NWARPS * 32)
#define MLP_BLOCKS 148
#define PI_F 3.14159265358979323846f

// feature rows: [0,200) ACSF (k*10+t), [200,300) APSF (k*10+t),
// [300] Zj, [301,311) onehot j, [311] Zk, [312,322) onehot k
#define FEAT 322
#define XROWS 328              // padded rows; each row is a float4 (4 pair slots)

// shared offsets (floats)
#define OFF_W1   0
#define OFF_W2   20608
#define OFF_W3   24704
#define OFF_WO   28800
#define OFF_B1   28864
#define OFF_G1   28928
#define OFF_BE1  28992
#define OFF_B2   29056
#define OFF_G2   29120
#define OFF_BE2  29184
#define OFF_B3   29248
#define OFF_G3   29312
#define OFF_BE3  29376
#define OFF_BO   29440
#define OFF_X    29444                              // 16B aligned
#define SMEM_FLOATS (OFF_X + NWARPS * XROWS * 4)    // 39940
#define SMEM_BYTES  (SMEM_FLOATS * 4)               // 159760

// ---------------- device globals ----------------
__device__ int    g_count;
__device__ int    g_done;
__device__ double g_sum;
__device__ int    g_p0[NPAIRS_MAX];
__device__ int    g_p1[NPAIRS_MAX];
__device__ float4 g_rec[NPAIRS_MAX];   // rij.x, rij.y, rij.z, w

__constant__ float c_zidx[10] = {1.f, 3.f, 5.f, 6.f, 7.f, 8.f, 9.f, 11.f, 15.f, 16.f};

// ---------------- helpers ----------------
__device__ __forceinline__ void box_inverse(const float* b, float* bi) {
    float det = b[0] * (b[4] * b[8] - b[5] * b[7])
              - b[1] * (b[3] * b[8] - b[5] * b[6])
              + b[2] * (b[3] * b[7] - b[4] * b[6]);
    float id = 1.f / det;
    bi[0] = (b[4] * b[8] - b[5] * b[7]) * id;
    bi[1] = (b[2] * b[7] - b[1] * b[8]) * id;
    bi[2] = (b[1] * b[5] - b[2] * b[4]) * id;
    bi[3] = (b[5] * b[6] - b[3] * b[8]) * id;
    bi[4] = (b[0] * b[8] - b[2] * b[6]) * id;
    bi[5] = (b[2] * b[3] - b[0] * b[5]) * id;
    bi[6] = (b[3] * b[7] - b[4] * b[6]) * id;
    bi[7] = (b[1] * b[6] - b[0] * b[7]) * id;
    bi[8] = (b[0] * b[4] - b[1] * b[3]) * id;
}

__device__ __forceinline__ float3 pbc3(float dx, float dy, float dz,
                                       const float* B, const float* Bi) {
    float s0 = dx * Bi[0] + dy * Bi[3] + dz * Bi[6];
    float s1 = dx * Bi[1] + dy * Bi[4] + dz * Bi[7];
    float s2 = dx * Bi[2] + dy * Bi[5] + dz * Bi[8];
    s0 -= floorf(s0 + 0.5f);
    s1 -= floorf(s1 + 0.5f);
    s2 -= floorf(s2 + 0.5f);
    float3 r;
    r.x = s0 * B[0] + s1 * B[3] + s2 * B[6];
    r.y = s0 * B[1] + s1 * B[4] + s2 * B[7];
    r.z = s0 * B[2] + s1 * B[5] + s2 * B[8];
    return r;
}

__device__ __forceinline__ float4 allreduce4(float4 v) {
#pragma unroll
    for (int o = 16; o > 0; o >>= 1) {
        v.x += __shfl_xor_sync(0xffffffffu, v.x, o);
        v.y += __shfl_xor_sync(0xffffffffu, v.y, o);
        v.z += __shfl_xor_sync(0xffffffffu, v.z, o);
        v.w += __shfl_xor_sync(0xffffffffu, v.w, o);
    }
    return v;
}

__device__ __forceinline__ void fma4(float4& a, const float4& x, float w) {
    a.x = fmaf(x.x, w, a.x); a.y = fmaf(x.y, w, a.y);
    a.z = fmaf(x.z, w, a.z); a.w = fmaf(x.w, w, a.w);
}
__device__ __forceinline__ float4 add4(const float4& a, const float4& b) {
    return make_float4(a.x + b.x, a.y + b.y, a.z + b.z, a.w + b.w);
}

// 4 pair-slots per warp, split accumulators (even/odd K) for ILP + shorter chains.
__device__ __forceinline__ void dense4(
    const float* __restrict__ Ws, const float* __restrict__ bb,
    const float* __restrict__ gg, const float* __restrict__ be,
    float* x, int inDim, int lane)
{
    float b0 = bb[lane], b1 = bb[lane + 32];
    float4 a0e = make_float4(b0, b0, b0, b0);
    float4 a1e = make_float4(b1, b1, b1, b1);
    float4 a0o = make_float4(0.f, 0.f, 0.f, 0.f);
    float4 a1o = make_float4(0.f, 0.f, 0.f, 0.f);
    const float* w0p = Ws + lane;
    const float* w1p = Ws + lane + 32;
#pragma unroll 2
    for (int i = 0; i < inDim; i += 2) {
        float4 xv0 = *(const float4*)(x + i * 4);
        float4 xv1 = *(const float4*)(x + (i + 1) * 4);
        float w00 = w0p[i * 64];
        float w10 = w1p[i * 64];
        float w01 = w0p[(i + 1) * 64];
        float w11 = w1p[(i + 1) * 64];
        fma4(a0e, xv0, w00); fma4(a1e, xv0, w10);
        fma4(a0o, xv1, w01); fma4(a1o, xv1, w11);
    }
    float4 a0 = add4(a0e, a0o);
    float4 a1 = add4(a1e, a1o);

    float4 s = add4(a0, a1);
    s = allreduce4(s);
    float4 mu = make_float4(s.x * (1.f/64.f), s.y * (1.f/64.f), s.z * (1.f/64.f), s.w * (1.f/64.f));
    float4 d0 = make_float4(a0.x - mu.x, a0.y - mu.y, a0.z - mu.z, a0.w - mu.w);
    float4 d1 = make_float4(a1.x - mu.x, a1.y - mu.y, a1.z - mu.z, a1.w - mu.w);
    float4 v = make_float4(d0.x*d0.x + d1.x*d1.x, d0.y*d0.y + d1.y*d1.y,
                           d0.z*d0.z + d1.z*d1.z, d0.w*d0.w + d1.w*d1.w);
    v = allreduce4(v);
    float4 r = make_float4(rsqrtf(v.x * (1.f/64.f) + 1e-6f),
                           rsqrtf(v.y * (1.f/64.f) + 1e-6f),
                           rsqrtf(v.z * (1.f/64.f) + 1e-6f),
                           rsqrtf(v.w * (1.f/64.f) + 1e-6f));
    float g0 = gg[lane], g1 = gg[lane + 32];
    float e0 = be[lane], e1 = be[lane + 32];
    float4 y0 = make_float4(fmaxf(d0.x * r.x * g0 + e0, 0.f),
                            fmaxf(d0.y * r.y * g0 + e0, 0.f),
                            fmaxf(d0.z * r.z * g0 + e0, 0.f),
                            fmaxf(d0.w * r.w * g0 + e0, 0.f));
    float4 y1 = make_float4(fmaxf(d1.x * r.x * g1 + e1, 0.f),
                            fmaxf(d1.y * r.y * g1 + e1, 0.f),
                            fmaxf(d1.z * r.z * g1 + e1, 0.f),
                            fmaxf(d1.w * r.w * g1 + e1, 0.f));
    __syncwarp();
    *(float4*)(x + lane * 4) = y0;
    *(float4*)(x + (lane + 32) * 4) = y1;
    __syncwarp();
}

// ---------------- kernel 1: filter + compact ----------------
__global__ void k_filter(const float* __restrict__ pos,
                         const float* __restrict__ box,
                         const float* __restrict__ valid,
                         const int* __restrict__ pairs,
                         const int* __restrict__ molid,
                         int npairs)
{
    int i = blockIdx.x * blockDim.x + threadIdx.x;
    if (i >= npairs) return;
    int p0 = pairs[3 * i];
    int p1 = pairs[3 * i + 1];
    if (p1 - p0 <= 0) { p0 -= 1; p1 -= 2; }
    if (p0 >= p1) return;
    if (__ldg(molid + p0) == __ldg(molid + p1)) return;
    float bs = __ldg(valid + i);
    if (bs == 0.f) return;

    float B[9], Bi[9];
#pragma unroll
    for (int k = 0; k < 9; k++) B[k] = box[k];
    box_inverse(B, Bi);

    float ax = __ldg(pos + 3 * p0), ay = __ldg(pos + 3 * p0 + 1), az = __ldg(pos + 3 * p0 + 2);
    float bx = __ldg(pos + 3 * p1), by = __ldg(pos + 3 * p1 + 1), bz = __ldg(pos + 3 * p1 + 2);
    float3 r = pbc3(bx - ax, by - ay, bz - az, B, Bi);
    float cx = r.x + 1e-10f, cy = r.y + 1e-10f, cz = r.z + 1e-10f;
    float dn = sqrtf(cx * cx + cy * cy + cz * cz);
    if (dn > 5.0f) return;
    float cut = 0.5f * (1.f + __cosf(PI_F * dn * (1.f / 5.f)));
    float w = bs * cut;
    if (w <= 0.f) return;

    int slot = atomicAdd(&g_count, 1);
    g_p0[slot] = p0;
    g_p1[slot] = p1;
    g_rec[slot] = make_float4(r.x, r.y, r.z, w);
}

// ---------------- kernel 2: features + MLP, 4 pairs per warp ----------------
__global__ __launch_bounds__(THREADS, 1)
void k_mlp(const float* __restrict__ pos,
           const float* __restrict__ box,
           const int* __restrict__ topo,
           const int* __restrict__ atype,
           const float* __restrict__ W1, const float* __restrict__ b1,
           const float* __restrict__ g1, const float* __restrict__ be1,
           const float* __restrict__ W2, const float* __restrict__ b2,
           const float* __restrict__ g2, const float* __restrict__ be2,
           const float* __restrict__ W3, const float* __restrict__ b3,
           const float* __restrict__ g3, const float* __restrict__ be3,
           const float* __restrict__ Wo, const float* __restrict__ bo,
           float* __restrict__ out)
{
    extern __shared__ float sm[];
    int tid = threadIdx.x;

    // stage weights (float4 copies)
    {
        const float4* W1v = (const float4*)W1;
        float4* s1 = (float4*)(sm + OFF_W1);
        for (int i = tid; i < 20608 / 4; i += THREADS) s1[i] = W1v[i];
        const float4* W2v = (const float4*)W2;
        const float4* W3v = (const float4*)W3;
        float4* s2 = (float4*)(sm + OFF_W2);
        float4* s3 = (float4*)(sm + OFF_W3);
        for (int i = tid; i < 1024; i += THREADS) { s2[i] = W2v[i]; s3[i] = W3v[i]; }
        if (tid < 64) {
            sm[OFF_WO + tid] = Wo[tid];
            sm[OFF_B1 + tid] = b1[tid]; sm[OFF_G1 + tid] = g1[tid]; sm[OFF_BE1 + tid] = be1[tid];
            sm[OFF_B2 + tid] = b2[tid]; sm[OFF_G2 + tid] = g2[tid]; sm[OFF_BE2 + tid] = be2[tid];
            sm[OFF_B3 + tid] = b3[tid]; sm[OFF_G3 + tid] = g3[tid]; sm[OFF_BE3 + tid] = be3[tid];
        }
        if (tid == 0) sm[OFF_BO] = bo[0];
    }
    __syncthreads();

    float B[9], Bi[9];
#pragma unroll
    for (int k = 0; k < 9; k++) B[k] = box[k];
    box_inverse(B, Bi);

    int lane = tid & 31;
    int wid = tid >> 5;
    float* x = sm + OFF_X + wid * (XROWS * 4);
    int n = g_count;
    int ngroups = (n + 3) >> 2;

    float mu_acsf = (float)lane * (5.f / 19.f);              // lanes 0..19
    float mu_apsf = -1.f + (float)(lane - 20) * (2.f / 9.f); // lanes 20..29

    // warp-spread mapping: every SM gets ~equal busy warps
    for (int grp = wid * gridDim.x + blockIdx.x; grp < ngroups;
         grp += gridDim.x * NWARPS) {
        int base = grp * 4;
        int np = n - base; if (np > 4) np = 4;

        int p0s[4], p1s[4];
        float uxs[4], uys[4], uzs[4], ws[4];
#pragma unroll
        for (int s = 0; s < 4; s++) {
            if (s < np) {
                p0s[s] = g_p0[base + s];
                p1s[s] = g_p1[base + s];
                float4 rc = g_rec[base + s];
                float cx = rc.x + 1e-10f, cy = rc.y + 1e-10f, cz = rc.z + 1e-10f;
                float r2 = cx * cx + cy * cy + cz * cz;
                float ui = rsqrtf(r2);                 // 1/dn (dn>0 guaranteed)
                float dn = r2 * ui;
                ui = 1.f / (dn + 1e-10f);
                uxs[s] = rc.x * ui; uys[s] = rc.y * ui; uzs[s] = rc.z * ui;
                ws[s] = rc.w;
            } else { p0s[s] = 0; p1s[s] = 0; uxs[s] = uys[s] = uzs[s] = 0.f; ws[s] = 0.f; }
        }

        // zero feature rows
        {
            float4 z = make_float4(0.f, 0.f, 0.f, 0.f);
            float4* xv = (float4*)x;
            for (int i = lane; i < XROWS; i += 32) xv[i] = z;
        }
        __syncwarp();

        // parallel gather: lanes 0..23 fetch neighbors for slots {0,1} (set A) and
        // {2,3} (set B); lanes 24..31 fetch the 8 pair-atom centers.
        int nbA = -1, tA = 0, nbB = -1, tB = 0;
        float xA = 0.f, yA = 0.f, zA = 0.f, xB = 0.f, yB = 0.f, zB = 0.f;
        float cpx = 0.f, cpy = 0.f, cpz = 0.f; int cpt = 0;
        if (lane < 24) {
            int pr = lane / 12;
            int e = lane % 12;
            int side = e / 6, m = e % 6;
            if (pr < np) {
                int a = side ? p1s[pr] : p0s[pr];
                nbA = __ldg(topo + a * MAX_NB + m);
            }
            int prB = pr + 2;
            if (prB < np) {
                int a = side ? p1s[prB] : p0s[prB];
                nbB = __ldg(topo + a * MAX_NB + m);
            }
        } else {
            int k = lane - 24;
            int slot = k >> 1, which = k & 1;
            if (slot < np) {
                int a = which ? p1s[slot] : p0s[slot];
                cpx = __ldg(pos + 3 * a); cpy = __ldg(pos + 3 * a + 1); cpz = __ldg(pos + 3 * a + 2);
                cpt = __ldg(atype + a);
            }
        }
        if (lane < 24) {
            if (nbA >= 0) { xA = __ldg(pos + 3 * nbA); yA = __ldg(pos + 3 * nbA + 1); zA = __ldg(pos + 3 * nbA + 2); tA = __ldg(atype + nbA); }
            if (nbB >= 0) { xB = __ldg(pos + 3 * nbB); yB = __ldg(pos + 3 * nbB + 1); zB = __ldg(pos + 3 * nbB + 2); tB = __ldg(atype + nbB); }
        }
        __syncwarp();

        // contribution loop: 4 slots x 12 edges
#pragma unroll
        for (int slot = 0; slot < 4; slot++) {
            if (slot >= np) break;
            int t0 = __shfl_sync(0xffffffffu, cpt, 24 + slot * 2);
            int t1 = __shfl_sync(0xffffffffu, cpt, 25 + slot * 2);
            float c0x = __shfl_sync(0xffffffffu, cpx, 24 + slot * 2);
            float c0y = __shfl_sync(0xffffffffu, cpy, 24 + slot * 2);
            float c0z = __shfl_sync(0xffffffffu, cpz, 24 + slot * 2);
            float c1x = __shfl_sync(0xffffffffu, cpx, 25 + slot * 2);
            float c1y = __shfl_sync(0xffffffffu, cpy, 25 + slot * 2);
            float c1z = __shfl_sync(0xffffffffu, cpz, 25 + slot * 2);
            float ux = uxs[slot], uy = uys[slot], uz = uzs[slot];
            float cw = ws[slot];
            int q0 = p0s[slot], q1 = p1s[slot];

            if (lane == 0) {
                x[300 * 4 + slot] = c_zidx[t0];
                x[(301 + t0) * 4 + slot] = 1.f;
                x[311 * 4 + slot] = c_zidx[t1];
                x[(312 + t1) * 4 + slot] = 1.f;
            }

            for (int e = 0; e < 12; e++) {
                int srcLane = (slot & 1) * 12 + e;
                int nbe, te; float ex, ey, ez;
                if (slot < 2) {
                    nbe = __shfl_sync(0xffffffffu, nbA, srcLane);
                    ex = __shfl_sync(0xffffffffu, xA, srcLane);
                    ey = __shfl_sync(0xffffffffu, yA, srcLane);
                    ez = __shfl_sync(0xffffffffu, zA, srcLane);
                    te = __shfl_sync(0xffffffffu, tA, srcLane);
                } else {
                    nbe = __shfl_sync(0xffffffffu, nbB, srcLane);
                    ex = __shfl_sync(0xffffffffu, xB, srcLane);
                    ey = __shfl_sync(0xffffffffu, yB, srcLane);
                    ez = __shfl_sync(0xffffffffu, zB, srcLane);
                    te = __shfl_sync(0xffffffffu, tB, srcLane);
                }
                if (nbe < 0) continue;                 // uniform branch
                int side = e / 6;
                float cx = side ? c1x : c0x;
                float cy = side ? c1y : c0y;
                float cz = side ? c1z : c0z;
                float3 d = pbc3(ex - cx, ey - cy, ez - cz, B, Bi);
                float ddx = d.x + 1e-10f, ddy = d.y + 1e-10f, ddz = d.z + 1e-10f;
                float r2 = ddx * ddx + ddy * ddy + ddz * ddz;
                float rinv = rsqrtf(r2);
                float edn = r2 * rinv;

                if (lane < 20) {
                    float fx = edn * 0.2f;
                    if (fx < 1.f) {
                        float fc = 0.5f * (__cosf(PI_F * fx) + 1.f);
                        float dm = edn - mu_acsf;
                        x[(lane * 10 + te) * 4 + slot] += 0.5f * fc * __expf(-100.f * dm * dm);
                    }
                } else if (lane < 30) {
                    if (nbe != q0 && nbe != q1) {
                        float sgn = side ? -1.f : 1.f;
                        float cg = (d.x * ux + d.y * uy + d.z * uz) * rinv * sgn;
                        float dm = cg - mu_apsf;
                        x[(200 + (lane - 20) * 10 + te) * 4 + slot] +=
                            0.5f * cw * __expf(-25.f * dm * dm);
                    }
                }
            }
        }
        __syncwarp();

        dense4(sm + OFF_W1, sm + OFF_B1, sm + OFF_G1, sm + OFF_BE1, x, FEAT, lane);
        dense4(sm + OFF_W2, sm + OFF_B2, sm + OFF_G2, sm + OFF_BE2, x, 64, lane);
        dense4(sm + OFF_W3, sm + OFF_B3, sm + OFF_G3, sm + OFF_BE3, x, 64, lane);

        float wo0 = sm[OFF_WO + lane], wo1 = sm[OFF_WO + lane + 32];
        float4 xv0 = *(const float4*)(x + lane * 4);
        float4 xv1 = *(const float4*)(x + (lane + 32) * 4);
        float4 v = make_float4(xv0.x * wo0 + xv1.x * wo1,
                               xv0.y * wo0 + xv1.y * wo1,
                               xv0.z * wo0 + xv1.z * wo1,
                               xv0.w * wo0 + xv1.w * wo1);
        v = allreduce4(v);
        if (lane == 0) {
            float bov = sm[OFF_BO];
            float tot = (v.x + bov) * ws[0] + (v.y + bov) * ws[1]
                      + (v.z + bov) * ws[2] + (v.w + bov) * ws[3];
            atomicAdd(&g_sum, (double)tot);
        }
    }

    // finalize: last block writes output and resets state for next graph replay
    __syncthreads();
    if (tid == 0) {
        __threadfence();
        int done = atomicAdd(&g_done, 1);
        if (done == (int)gridDim.x - 1) {
            double s = atomicAdd(&g_sum, 0.0);   // coherent read
            out[0] = (float)s;
            g_sum = 0.0;
            g_count = 0;
            g_done = 0;
        }
    }
}

// ---------------- launch ----------------
extern "C" void kernel_launch(void* const* d_in, const int* in_sizes, int n_in,
                              void* d_out, int out_size)
{
    const float* pos   = (const float*)d_in[0];
    const float* box   = (const float*)d_in[1];
    const float* valid = (const float*)d_in[2];
    const float* W1 = (const float*)d_in[3];
    const float* b1 = (const float*)d_in[4];
    const float* g1 = (const float*)d_in[5];
    const float* be1 = (const float*)d_in[6];
    const float* W2 = (const float*)d_in[7];
    const float* b2 = (const float*)d_in[8];
    const float* g2 = (const float*)d_in[9];
    const float* be2 = (const float*)d_in[10];
    const float* W3 = (const float*)d_in[11];
    const float* b3 = (const float*)d_in[12];
    const float* g3 = (const float*)d_in[13];
    const float* be3 = (const float*)d_in[14];
    const float* Wo = (const float*)d_in[15];
    const float* bo = (const float*)d_in[16];
    const int* pairs = (const int*)d_in[17];
    const int* topo  = (const int*)d_in[18];
    // d_in[19] topo_mask: redundant with topo != -1
    const int* molid = (const int*)d_in[20];
    const int* atype = (const int*)d_in[21];

    int npairs = in_sizes[17] / 3;
    if (npairs > NPAIRS_MAX) npairs = NPAIRS_MAX;

    cudaFuncSetAttribute(k_mlp, cudaFuncAttributeMaxDynamicSharedMemorySize, SMEM_BYTES);

    k_filter<<<(npairs + 255) / 256, 256>>>(pos, box, valid, pairs, molid, npairs);
    k_mlp<<<MLP_BLOCKS, THREADS, SMEM_BYTES>>>(pos, box, topo, atype,
        W1, b1, g1, be1, W2, b2, g2, be2, W3, b3, g3, be3, Wo, bo,
        (float*)d_out);
}

// round 6
// speedup vs baseline: 1.6423x; 1.0008x over previous
#include <cuda_runtime.h>
#include <math.h>
#include <stdint.h>

// ---------------- problem constants ----------------
#define NPAIRS_MAX 200000
#define MAX_NB 6
#define NWARPS 8
#define THREADS (NWARPS * 32)
#define MLP_BLOCKS 148
#define PI_F 3.14159265358979323846f

#define FEAT 322
#define XROWS 328              // padded rows; each row is a float4 (4 pair slots)

// shared offsets (floats); W1/W2/W3 stored INTERLEAVED: (i*32+o) as float2 = (W[i][o], W[i][o+32])
#define OFF_W1   0
#define OFF_W2   20608
#define OFF_W3   24704
#define OFF_WO   28800
#define OFF_B1   28864
#define OFF_G1   28928
#define OFF_BE1  28992
#define OFF_B2   29056
#define OFF_G2   29120
#define OFF_BE2  29184
#define OFF_B3   29248
#define OFF_G3   29312
#define OFF_BE3  29376
#define OFF_BO   29440
#define OFF_X    29444                              // 16B aligned
#define SMEM_FLOATS (OFF_X + NWARPS * XROWS * 4)    // 39940
#define SMEM_BYTES  (SMEM_FLOATS * 4)               // 159760

// ---------------- device globals ----------------
__device__ int    g_count;
__device__ int    g_done;
__device__ double g_sum;
__device__ int    g_p0[NPAIRS_MAX];
__device__ int    g_p1[NPAIRS_MAX];
__device__ float4 g_rec[NPAIRS_MAX];   // rij.x, rij.y, rij.z, w

__constant__ float c_zidx[10] = {1.f, 3.f, 5.f, 6.f, 7.f, 8.f, 9.f, 11.f, 15.f, 16.f};

// ---------------- helpers ----------------
__device__ __forceinline__ void box_inverse(const float* b, float* bi) {
    float det = b[0] * (b[4] * b[8] - b[5] * b[7])
              - b[1] * (b[3] * b[8] - b[5] * b[6])
              + b[2] * (b[3] * b[7] - b[4] * b[6]);
    float id = 1.f / det;
    bi[0] = (b[4] * b[8] - b[5] * b[7]) * id;
    bi[1] = (b[2] * b[7] - b[1] * b[8]) * id;
    bi[2] = (b[1] * b[5] - b[2] * b[4]) * id;
    bi[3] = (b[5] * b[6] - b[3] * b[8]) * id;
    bi[4] = (b[0] * b[8] - b[2] * b[6]) * id;
    bi[5] = (b[2] * b[3] - b[0] * b[5]) * id;
    bi[6] = (b[3] * b[7] - b[4] * b[6]) * id;
    bi[7] = (b[1] * b[6] - b[0] * b[7]) * id;
    bi[8] = (b[0] * b[4] - b[1] * b[3]) * id;
}

__device__ __forceinline__ float3 pbc3(float dx, float dy, float dz,
                                       const float* B, const float* Bi) {
    float s0 = dx * Bi[0] + dy * Bi[3] + dz * Bi[6];
    float s1 = dx * Bi[1] + dy * Bi[4] + dz * Bi[7];
    float s2 = dx * Bi[2] + dy * Bi[5] + dz * Bi[8];
    s0 -= floorf(s0 + 0.5f);
    s1 -= floorf(s1 + 0.5f);
    s2 -= floorf(s2 + 0.5f);
    float3 r;
    r.x = s0 * B[0] + s1 * B[3] + s2 * B[6];
    r.y = s0 * B[1] + s1 * B[4] + s2 * B[7];
    r.z = s0 * B[2] + s1 * B[5] + s2 * B[8];
    return r;
}

__device__ __forceinline__ float4 allreduce4(float4 v) {
#pragma unroll
    for (int o = 16; o > 0; o >>= 1) {
        v.x += __shfl_xor_sync(0xffffffffu, v.x, o);
        v.y += __shfl_xor_sync(0xffffffffu, v.y, o);
        v.z += __shfl_xor_sync(0xffffffffu, v.z, o);
        v.w += __shfl_xor_sync(0xffffffffu, v.w, o);
    }
    return v;
}

__device__ __forceinline__ void fma4(float4& a, const float4& x, float w) {
    a.x = fmaf(x.x, w, a.x); a.y = fmaf(x.y, w, a.y);
    a.z = fmaf(x.z, w, a.z); a.w = fmaf(x.w, w, a.w);
}
__device__ __forceinline__ float4 add4(const float4& a, const float4& b) {
    return make_float4(a.x + b.x, a.y + b.y, a.z + b.z, a.w + b.w);
}

// 4 pair-slots per warp, interleaved weights (LDS.64), split even/odd accumulators.
__device__ __forceinline__ void dense4i(
    const float* __restrict__ Wi, const float* __restrict__ bb,
    const float* __restrict__ gg, const float* __restrict__ be,
    float* x, int inDim, int lane)
{
    float b0 = bb[lane], b1 = bb[lane + 32];
    float4 a0e = make_float4(b0, b0, b0, b0);
    float4 a1e = make_float4(b1, b1, b1, b1);
    float4 a0o = make_float4(0.f, 0.f, 0.f, 0.f);
    float4 a1o = make_float4(0.f, 0.f, 0.f, 0.f);
    const float2* wp = (const float2*)Wi + lane;
#pragma unroll 4
    for (int i = 0; i < inDim; i += 2) {
        float4 xv0 = *(const float4*)(x + i * 4);
        float4 xv1 = *(const float4*)(x + (i + 1) * 4);
        float2 w0 = wp[i * 32];
        float2 w1 = wp[(i + 1) * 32];
        fma4(a0e, xv0, w0.x); fma4(a1e, xv0, w0.y);
        fma4(a0o, xv1, w1.x); fma4(a1o, xv1, w1.y);
    }
    float4 a0 = add4(a0e, a0o);
    float4 a1 = add4(a1e, a1o);

    float4 s = add4(a0, a1);
    s = allreduce4(s);
    float4 mu = make_float4(s.x * (1.f/64.f), s.y * (1.f/64.f), s.z * (1.f/64.f), s.w * (1.f/64.f));
    float4 d0 = make_float4(a0.x - mu.x, a0.y - mu.y, a0.z - mu.z, a0.w - mu.w);
    float4 d1 = make_float4(a1.x - mu.x, a1.y - mu.y, a1.z - mu.z, a1.w - mu.w);
    float4 v = make_float4(d0.x*d0.x + d1.x*d1.x, d0.y*d0.y + d1.y*d1.y,
                           d0.z*d0.z + d1.z*d1.z, d0.w*d0.w + d1.w*d1.w);
    v = allreduce4(v);
    float4 r = make_float4(rsqrtf(v.x * (1.f/64.f) + 1e-6f),
                           rsqrtf(v.y * (1.f/64.f) + 1e-6f),
                           rsqrtf(v.z * (1.f/64.f) + 1e-6f),
                           rsqrtf(v.w * (1.f/64.f) + 1e-6f));
    float g0 = gg[lane], g1 = gg[lane + 32];
    float e0 = be[lane], e1 = be[lane + 32];
    float4 y0 = make_float4(fmaxf(d0.x * r.x * g0 + e0, 0.f),
                            fmaxf(d0.y * r.y * g0 + e0, 0.f),
                            fmaxf(d0.z * r.z * g0 + e0, 0.f),
                            fmaxf(d0.w * r.w * g0 + e0, 0.f));
    float4 y1 = make_float4(fmaxf(d1.x * r.x * g1 + e1, 0.f),
                            fmaxf(d1.y * r.y * g1 + e1, 0.f),
                            fmaxf(d1.z * r.z * g1 + e1, 0.f),
                            fmaxf(d1.w * r.w * g1 + e1, 0.f));
    __syncwarp();
    *(float4*)(x + lane * 4) = y0;
    *(float4*)(x + (lane + 32) * 4) = y1;
    __syncwarp();
}

// ---------------- kernel 1: filter + compact ----------------
__global__ void k_filter(const float* __restrict__ pos,
                         const float* __restrict__ box,
                         const float* __restrict__ valid,
                         const int* __restrict__ pairs,
                         const int* __restrict__ molid,
                         int npairs)
{
    int i = blockIdx.x * blockDim.x + threadIdx.x;
    if (i >= npairs) return;
    int p0 = pairs[3 * i];
    int p1 = pairs[3 * i + 1];
    if (p1 - p0 <= 0) { p0 -= 1; p1 -= 2; }
    if (p0 >= p1) return;
    if (__ldg(molid + p0) == __ldg(molid + p1)) return;
    float bs = __ldg(valid + i);
    if (bs == 0.f) return;

    float B[9], Bi[9];
#pragma unroll
    for (int k = 0; k < 9; k++) B[k] = box[k];
    box_inverse(B, Bi);

    float ax = __ldg(pos + 3 * p0), ay = __ldg(pos + 3 * p0 + 1), az = __ldg(pos + 3 * p0 + 2);
    float bx = __ldg(pos + 3 * p1), by = __ldg(pos + 3 * p1 + 1), bz = __ldg(pos + 3 * p1 + 2);
    float3 r = pbc3(bx - ax, by - ay, bz - az, B, Bi);
    float cx = r.x + 1e-10f, cy = r.y + 1e-10f, cz = r.z + 1e-10f;
    float dn = sqrtf(cx * cx + cy * cy + cz * cz);
    if (dn > 5.0f) return;
    float cut = 0.5f * (1.f + __cosf(PI_F * dn * (1.f / 5.f)));
    float w = bs * cut;
    if (w <= 0.f) return;

    int slot = atomicAdd(&g_count, 1);
    g_p0[slot] = p0;
    g_p1[slot] = p1;
    g_rec[slot] = make_float4(r.x, r.y, r.z, w);
}

// edge setup for one batch (slots SLO, SHI): lanes 0..23 compute their edge's
// scalars in PARALLEL; all other lanes produce zeros.
#define EDGE_SETUP(ednR, cfaR, cgR, cfpR, teR, SLO, SHI)                      \
{                                                                             \
    ednR = 0.f; cfaR = 0.f; cgR = 0.f; cfpR = 0.f; teR = 0;                   \
    if (lane < 24) {                                                          \
        int hi   = (lane >= 12);                                              \
        int side = (lane % 12) >= 6;                                          \
        int m    = lane % 6;                                                  \
        int slot = hi ? (SHI) : (SLO);                                        \
        int qq0  = hi ? p0s[SHI] : p0s[SLO];                                  \
        int qq1  = hi ? p1s[SHI] : p1s[SLO];                                  \
        float ux = hi ? uxs[SHI] : uxs[SLO];                                  \
        float uy = hi ? uys[SHI] : uys[SLO];                                  \
        float uz = hi ? uzs[SHI] : uzs[SLO];                                  \
        float wv = hi ? ws[SHI]  : ws[SLO];                                   \
        int a = side ? qq1 : qq0;                                             \
        int nb = __ldg(topo + a * MAX_NB + m);                                \
        if (nb >= 0 && slot < np) {                                           \
            float ccx = __ldg(pos + 3 * a);                                   \
            float ccy = __ldg(pos + 3 * a + 1);                               \
            float ccz = __ldg(pos + 3 * a + 2);                               \
            float enx = __ldg(pos + 3 * nb);                                  \
            float eny = __ldg(pos + 3 * nb + 1);                              \
            float enz = __ldg(pos + 3 * nb + 2);                              \
            teR = __ldg(atype + nb);                                          \
            float3 d = pbc3(enx - ccx, eny - ccy, enz - ccz, B, Bi);          \
            float ddx = d.x + 1e-10f, ddy = d.y + 1e-10f, ddz = d.z + 1e-10f; \
            float r2 = ddx * ddx + ddy * ddy + ddz * ddz;                     \
            float rinv = rsqrtf(r2);                                          \
            float edn = r2 * rinv;                                            \
            ednR = edn;                                                       \
            float fx = edn * 0.2f;                                            \
            if (fx < 1.f) cfaR = 0.25f * (__cosf(PI_F * fx) + 1.f);           \
            float sgn = side ? -1.f : 1.f;                                    \
            cgR = (d.x * ux + d.y * uy + d.z * uz) * rinv * sgn;              \
            if (nb != qq0 && nb != qq1) cfpR = 0.5f * wv;                     \
        }                                                                     \
    }                                                                         \
}

// apply 24 edges of one batch: per edge only shuffles + exp + RMW (independent chains)
#define EDGE_APPLY(ednR, cfaR, cgR, cfpR, teR, SLO, SHI)                      \
{                                                                             \
    _Pragma("unroll 8")                                                       \
    for (int e = 0; e < 24; e++) {                                            \
        float ca = __shfl_sync(0xffffffffu, cfaR, e);                         \
        float cp = __shfl_sync(0xffffffffu, cfpR, e);                         \
        if (ca == 0.f && cp == 0.f) continue;                                 \
        float edn = __shfl_sync(0xffffffffu, ednR, e);                        \
        float cg  = __shfl_sync(0xffffffffu, cgR, e);                         \
        int   te  = __shfl_sync(0xffffffffu, teR, e);                         \
        int slot = (e < 12) ? (SLO) : (SHI);                                  \
        if (lane < 20) {                                                      \
            if (ca != 0.f) {                                                  \
                float dm = edn - mu_acsf;                                     \
                x[(lane * 10 + te) * 4 + slot] += ca * __expf(-100.f * dm * dm); \
            }                                                                 \
        } else if (lane < 30) {                                               \
            if (cp != 0.f) {                                                  \
                float dm = cg - mu_apsf;                                      \
                x[(200 + (lane - 20) * 10 + te) * 4 + slot] +=                \
                    cp * __expf(-25.f * dm * dm);                             \
            }                                                                 \
        }                                                                     \
    }                                                                         \
}

// ---------------- kernel 2: features + MLP, 4 pairs per warp ----------------
__global__ __launch_bounds__(THREADS, 1)
void k_mlp(const float* __restrict__ pos,
           const float* __restrict__ box,
           const int* __restrict__ topo,
           const int* __restrict__ atype,
           const float* __restrict__ W1, const float* __restrict__ b1,
           const float* __restrict__ g1, const float* __restrict__ be1,
           const float* __restrict__ W2, const float* __restrict__ b2,
           const float* __restrict__ g2, const float* __restrict__ be2,
           const float* __restrict__ W3, const float* __restrict__ b3,
           const float* __restrict__ g3, const float* __restrict__ be3,
           const float* __restrict__ Wo, const float* __restrict__ bo,
           float* __restrict__ out)
{
    extern __shared__ float sm[];
    int tid = threadIdx.x;

    // stage weights INTERLEAVED: sm[i*64 + 2*o] = W[i][o], sm[i*64 + 2*o+1] = W[i][o+32]
    for (int idx = tid; idx < 20608; idx += THREADS) {
        int i = idx >> 6, o = idx & 63;
        int p = (o < 32) ? (o * 2) : ((o - 32) * 2 + 1);
        sm[OFF_W1 + (i << 6) + p] = __ldg(W1 + idx);
    }
    for (int idx = tid; idx < 4096; idx += THREADS) {
        int i = idx >> 6, o = idx & 63;
        int p = (o < 32) ? (o * 2) : ((o - 32) * 2 + 1);
        sm[OFF_W2 + (i << 6) + p] = __ldg(W2 + idx);
        sm[OFF_W3 + (i << 6) + p] = __ldg(W3 + idx);
    }
    if (tid < 64) {
        sm[OFF_WO + tid] = Wo[tid];
        sm[OFF_B1 + tid] = b1[tid]; sm[OFF_G1 + tid] = g1[tid]; sm[OFF_BE1 + tid] = be1[tid];
        sm[OFF_B2 + tid] = b2[tid]; sm[OFF_G2 + tid] = g2[tid]; sm[OFF_BE2 + tid] = be2[tid];
        sm[OFF_B3 + tid] = b3[tid]; sm[OFF_G3 + tid] = g3[tid]; sm[OFF_BE3 + tid] = be3[tid];
    }
    if (tid == 0) sm[OFF_BO] = bo[0];
    __syncthreads();

    float B[9], Bi[9];
#pragma unroll
    for (int k = 0; k < 9; k++) B[k] = box[k];
    box_inverse(B, Bi);

    int lane = tid & 31;
    int wid = tid >> 5;
    float* x = sm + OFF_X + wid * (XROWS * 4);
    int n = g_count;
    int ngroups = (n + 3) >> 2;

    float mu_acsf = (float)lane * (5.f / 19.f);              // lanes 0..19
    float mu_apsf = -1.f + (float)(lane - 20) * (2.f / 9.f); // lanes 20..29

    for (int grp = wid * gridDim.x + blockIdx.x; grp < ngroups;
         grp += gridDim.x * NWARPS) {
        int base = grp * 4;
        int np = n - base; if (np > 4) np = 4;

        int p0s[4], p1s[4];
        float uxs[4], uys[4], uzs[4], ws[4];
#pragma unroll
        for (int s = 0; s < 4; s++) {
            if (s < np) {
                p0s[s] = g_p0[base + s];
                p1s[s] = g_p1[base + s];
                float4 rc = g_rec[base + s];
                float cx = rc.x + 1e-10f, cy = rc.y + 1e-10f, cz = rc.z + 1e-10f;
                float r2 = cx * cx + cy * cy + cz * cz;
                float ui = rsqrtf(r2);
                float dn = r2 * ui;
                ui = 1.f / (dn + 1e-10f);
                uxs[s] = rc.x * ui; uys[s] = rc.y * ui; uzs[s] = rc.z * ui;
                ws[s] = rc.w;
            } else { p0s[s] = 0; p1s[s] = 0; uxs[s] = uys[s] = uzs[s] = 0.f; ws[s] = 0.f; }
        }

        // parallel edge setup for both batches (slots {0,1} then {2,3})
        float ednA, cfaA, cgA, cfpA; int teA;
        float ednB, cfaB, cgB, cfpB; int teB;
        EDGE_SETUP(ednA, cfaA, cgA, cfpA, teA, 0, 1);
        EDGE_SETUP(ednB, cfaB, cgB, cfpB, teB, 2, 3);

        // pair-atom types for the one-hot block (lanes 24..31)
        int cpt = 0;
        if (lane >= 24) {
            int k = lane - 24;
            int slot = k >> 1, which = k & 1;
            if (slot < np) {
                int a = which ? p1s[slot] : p0s[slot];
                cpt = __ldg(atype + a);
            }
        }

        // zero feature rows
        {
            float4 z = make_float4(0.f, 0.f, 0.f, 0.f);
            float4* xv = (float4*)x;
            for (int i = lane; i < XROWS; i += 32) xv[i] = z;
        }
        __syncwarp();

        // one-hot/element block
#pragma unroll
        for (int slot = 0; slot < 4; slot++) {
            if (slot >= np) break;
            int t0 = __shfl_sync(0xffffffffu, cpt, 24 + slot * 2);
            int t1 = __shfl_sync(0xffffffffu, cpt, 25 + slot * 2);
            if (lane == 0) {
                x[300 * 4 + slot] = c_zidx[t0];
                x[(301 + t0) * 4 + slot] = 1.f;
                x[311 * 4 + slot] = c_zidx[t1];
                x[(312 + t1) * 4 + slot] = 1.f;
            }
        }

        // apply edges (independent short chains per iteration)
        EDGE_APPLY(ednA, cfaA, cgA, cfpA, teA, 0, 1);
        EDGE_APPLY(ednB, cfaB, cgB, cfpB, teB, 2, 3);
        __syncwarp();

        dense4i(sm + OFF_W1, sm + OFF_B1, sm + OFF_G1, sm + OFF_BE1, x, FEAT, lane);
        dense4i(sm + OFF_W2, sm + OFF_B2, sm + OFF_G2, sm + OFF_BE2, x, 64, lane);
        dense4i(sm + OFF_W3, sm + OFF_B3, sm + OFF_G3, sm + OFF_BE3, x, 64, lane);

        float wo0 = sm[OFF_WO + lane], wo1 = sm[OFF_WO + lane + 32];
        float4 xv0 = *(const float4*)(x + lane * 4);
        float4 xv1 = *(const float4*)(x + (lane + 32) * 4);
        float4 v = make_float4(xv0.x * wo0 + xv1.x * wo1,
                               xv0.y * wo0 + xv1.y * wo1,
                               xv0.z * wo0 + xv1.z * wo1,
                               xv0.w * wo0 + xv1.w * wo1);
        v = allreduce4(v);
        if (lane == 0) {
            float bov = sm[OFF_BO];
            float tot = (v.x + bov) * ws[0] + (v.y + bov) * ws[1]
                      + (v.z + bov) * ws[2] + (v.w + bov) * ws[3];
            atomicAdd(&g_sum, (double)tot);
        }
    }

    // finalize: last block writes output and resets state for next graph replay
    __syncthreads();
    if (tid == 0) {
        __threadfence();
        int done = atomicAdd(&g_done, 1);
        if (done == (int)gridDim.x - 1) {
            double s = atomicAdd(&g_sum, 0.0);   // coherent read
            out[0] = (float)s;
            g_sum = 0.0;
            g_count = 0;
            g_done = 0;
        }
    }
}

// ---------------- launch ----------------
extern "C" void kernel_launch(void* const* d_in, const int* in_sizes, int n_in,
                              void* d_out, int out_size)
{
    const float* pos   = (const float*)d_in[0];
    const float* box   = (const float*)d_in[1];
    const float* valid = (const float*)d_in[2];
    const float* W1 = (const float*)d_in[3];
    const float* b1 = (const float*)d_in[4];
    const float* g1 = (const float*)d_in[5];
    const float* be1 = (const float*)d_in[6];
    const float* W2 = (const float*)d_in[7];
    const float* b2 = (const float*)d_in[8];
    const float* g2 = (const float*)d_in[9];
    const float* be2 = (const float*)d_in[10];
    const float* W3 = (const float*)d_in[11];
    const float* b3 = (const float*)d_in[12];
    const float* g3 = (const float*)d_in[13];
    const float* be3 = (const float*)d_in[14];
    const float* Wo = (const float*)d_in[15];
    const float* bo = (const float*)d_in[16];
    const int* pairs = (const int*)d_in[17];
    const int* topo  = (const int*)d_in[18];
    // d_in[19] topo_mask: redundant with topo != -1
    const int* molid = (const int*)d_in[20];
    const int* atype = (const int*)d_in[21];

    int npairs = in_sizes[17] / 3;
    if (npairs > NPAIRS_MAX) npairs = NPAIRS_MAX;

    cudaFuncSetAttribute(k_mlp, cudaFuncAttributeMaxDynamicSharedMemorySize, SMEM_BYTES);

    k_filter<<<(npairs + 255) / 256, 256>>>(pos, box, valid, pairs, molid, npairs);
    k_mlp<<<MLP_BLOCKS, THREADS, SMEM_BYTES>>>(pos, box, topo, atype,
        W1, b1, g1, be1, W2, b2, g2, be2, W3, b3, g3, be3, Wo, bo,
        (float*)d_out);
}